// round 6
// baseline (speedup 1.0000x reference)
#include <cuda_runtime.h>
#include <cuda_bf16.h>
#include <cstdint>
#include <math.h>

// ----------------------------------------------------------------------------
// B=16384, D=512, H=256, R=95, KJ=64. TB=128 rows/CTA, 1024 threads (32 warps,
// 8m x 4n warp grid, warp tile 16x64), 1 CTA/SM. mma.sync m16n8k16 bf16,
// hi/lo split (3 products). Double-buffered k-chunk-32 staging.
// ----------------------------------------------------------------------------

#define TB 128
#define NT 1024

// staging buffer internal offsets (bytes), stride 80 per row
#define S_AHI 0        // A hi [128][80] = 10240
#define S_ALO 10240    // A lo
#define S_BHI 20480    // B hi [256][80] = 20480
#define S_BLO 40960    // B lo
#define S_BUF 61440    // per-buffer; buf0 @0, buf1 @61440

// region reuse: X slabs overlay staging after GEMM1
#define OFF_X    0            // x hi [4 wn][128][128B] = 65536, lo at +65536
#define XLO      65536
#define OFF_MB   131072       // mbuf [2][128][65] f32 = 66560
#define OFF_TB   197632       // Tbuf [64][97] f32 = 24832
#define OFF_ST   222464       // stats [128][8] f32 = 4096
#define SMEM_BYTES 226560

#define SW(x) ((x) ^ (((x) >> 3) & 0x70))

static __device__ __forceinline__ uint32_t smem_u32(const void* p) {
    uint32_t a;
    asm("{ .reg .u64 t; cvta.to.shared.u64 t, %1; cvt.u32.u64 %0, t; }" : "=r"(a) : "l"(p));
    return a;
}

static __device__ __forceinline__ void ldsm4(uint32_t* r, uint32_t addr) {
    asm volatile("ldmatrix.sync.aligned.m8n8.x4.shared.b16 {%0,%1,%2,%3}, [%4];"
                 : "=r"(r[0]), "=r"(r[1]), "=r"(r[2]), "=r"(r[3]) : "r"(addr));
}

static __device__ __forceinline__ void mma16816(float* c, const uint32_t* a,
                                                uint32_t b0, uint32_t b1) {
    asm volatile(
        "mma.sync.aligned.m16n8k16.row.col.f32.bf16.bf16.f32 "
        "{%0,%1,%2,%3}, {%4,%5,%6,%7}, {%8,%9}, {%0,%1,%2,%3};"
        : "+f"(c[0]), "+f"(c[1]), "+f"(c[2]), "+f"(c[3])
        : "r"(a[0]), "r"(a[1]), "r"(a[2]), "r"(a[3]), "r"(b0), "r"(b1));
}

static __device__ __forceinline__ void cp16(uint32_t dst, const void* src) {
    asm volatile("cp.async.cg.shared.global [%0], [%1], 16;" :: "r"(dst), "l"(src));
}

// hi/lo bf16 split of a float pair, packed (elem0 in low half)
static __device__ __forceinline__ void split2(float a0, float a1, uint32_t& hi, uint32_t& lo) {
    __nv_bfloat16 h0 = __float2bfloat16_rn(a0), h1 = __float2bfloat16_rn(a1);
    float f0 = __bfloat162float(h0), f1 = __bfloat162float(h1);
    __nv_bfloat16 l0 = __float2bfloat16_rn(a0 - f0), l1 = __float2bfloat16_rn(a1 - f1);
    hi = ((uint32_t)__bfloat16_as_ushort(h1) << 16) | (uint32_t)__bfloat16_as_ushort(h0);
    lo = ((uint32_t)__bfloat16_as_ushort(l1) << 16) | (uint32_t)__bfloat16_as_ushort(l0);
}

// weight scratch: W1^T u32[n=256][kp=256], W2^T u32[n=64][kp=128]  (kp = k/2 pairs)
__device__ __align__(16) uint32_t g_w1t_hi[2][256 * 256];
__device__ __align__(16) uint32_t g_w1t_lo[2][256 * 256];
__device__ __align__(16) uint32_t g_w2t_hi[2][64 * 128];
__device__ __align__(16) uint32_t g_w2t_lo[2][64 * 128];

__global__ void prep_kernel(const float* __restrict__ Wp1, const float* __restrict__ Wv1,
                            const float* __restrict__ Wp2, const float* __restrict__ Wv2) {
    int idx = blockIdx.x * blockDim.x + threadIdx.x;
    if (idx < 65536) {
        int n = idx >> 8, kp = idx & 255;
#pragma unroll
        for (int p = 0; p < 2; ++p) {
            const float* W1 = p ? Wv1 : Wp1;
            float a0 = W1[(2 * kp) * 256 + n];
            float a1 = W1[(2 * kp + 1) * 256 + n];
            uint32_t hi, lo;
            split2(a0, a1, hi, lo);
            g_w1t_hi[p][n * 256 + kp] = hi;
            g_w1t_lo[p][n * 256 + kp] = lo;
        }
    } else if (idx < 65536 + 8192) {
        int j = idx - 65536;
        int n = j >> 7, kp = j & 127;
#pragma unroll
        for (int p = 0; p < 2; ++p) {
            const float* W2 = p ? Wv2 : Wp2;
            float a0 = W2[(2 * kp) * 64 + n];
            float a1 = W2[(2 * kp + 1) * 64 + n];
            uint32_t hi, lo;
            split2(a0, a1, hi, lo);
            g_w2t_hi[p][n * 128 + kp] = hi;
            g_w2t_lo[p][n * 128 + kp] = lo;
        }
    }
}

__global__ __launch_bounds__(NT, 1)
void clifford_mma_kernel(
    const float* __restrict__ h_perp, const float* __restrict__ h_vuln,
    const float* __restrict__ bp1, const float* __restrict__ lgp,
    const float* __restrict__ lbp, const float* __restrict__ bp2,
    const float* __restrict__ bv1, const float* __restrict__ lgv,
    const float* __restrict__ lbv, const float* __restrict__ bv2,
    const float* __restrict__ Tm, const float* __restrict__ gw,
    float* __restrict__ out)
{
    extern __shared__ char smem[];
    const uint32_t sb = smem_u32(smem);
    const int tid = threadIdx.x;
    const int lane = tid & 31;
    const int wid = tid >> 5;     // 0..31
    const int wm = wid & 7;       // m-block: rows wm*16..+16
    const int wn = wid >> 3;      // n-block: cols wn*64..+64
    const int g = lane >> 2, t = lane & 3;
    const int g8 = lane & 7, m4 = lane >> 3;
    const int r0 = blockIdx.x * TB;

    float* mbuf  = (float*)(smem + OFF_MB);
    float* Tbuf  = (float*)(smem + OFF_TB);
    float* stats = (float*)(smem + OFF_ST);

    // stage T^T scaled by 1/8 (region never overlaps staging)
    for (int i = tid; i < 95 * 64; i += NT) {
        int r = i >> 6, kj = i & 63;
        Tbuf[kj * 97 + r] = Tm[i] * 0.125f;
    }

    for (int p = 0; p < 2; ++p) {
        const float* hsrc = p ? h_vuln : h_perp;
        const uint32_t* w1h = g_w1t_hi[p];
        const uint32_t* w1l = g_w1t_lo[p];
        const uint32_t* w2h = g_w2t_hi[p];
        const uint32_t* w2l = g_w2t_lo[p];
        const float* b1 = p ? bv1 : bp1;
        const float* lg = p ? lgv : lgp;
        const float* lb = p ? lbv : lbp;
        const float* b2 = p ? bv2 : bp2;

        // ===== GEMM1: acc[128,256] = h @ W1, warp tile 16x64, k-chunk 32, dbuf =====
        float acc[8][4];
#pragma unroll
        for (int j = 0; j < 8; ++j)
#pragma unroll
            for (int q = 0; q < 4; ++q) acc[j][q] = 0.f;

        // staging mapping: A: 1024 float4 -> 1/thread (row=tid>>3, q=tid&7)
        //                  B: 1024 (row,q) pairs -> 1/thread (row=tid>>2, q=tid&3)
        const int a_row = tid >> 3, a_q = tid & 7;
        const int b_row = tid >> 2, b_q = tid & 3;

        // ---- prologue: stage chunk 0 into buf0 ----
        {
            uint32_t dsto = (uint32_t)(b_row * 80 + b_q * 16);
            cp16(sb + S_BHI + dsto, w1h + b_row * 256 + b_q * 4);
            cp16(sb + S_BLO + dsto, w1l + b_row * 256 + b_q * 4);
            asm volatile("cp.async.commit_group;");
            float4 v = *(const float4*)(hsrc + (size_t)(r0 + a_row) * 512 + a_q * 4);
            uint32_t h0, l0, h1, l1;
            split2(v.x, v.y, h0, l0);
            split2(v.z, v.w, h1, l1);
            char* base = smem + a_row * 80 + a_q * 8;
            *(uint2*)(base + S_AHI) = make_uint2(h0, h1);
            *(uint2*)(base + S_ALO) = make_uint2(l0, l1);
        }

        float4 va;
        for (int kc = 0; kc < 16; ++kc) {
            const uint32_t cbuf = sb + (uint32_t)((kc & 1) * S_BUF);
            const uint32_t nbuf = sb + (uint32_t)(((kc + 1) & 1) * S_BUF);
            __syncthreads();   // prev chunk's MMA reads + this chunk's STS all done

            if (kc < 15) {
                const int kn = (kc + 1) * 32;
                uint32_t dsto = (uint32_t)(b_row * 80 + b_q * 16);
                cp16(nbuf + S_BHI + dsto, w1h + b_row * 256 + (kn >> 1) + b_q * 4);
                cp16(nbuf + S_BLO + dsto, w1l + b_row * 256 + (kn >> 1) + b_q * 4);
                asm volatile("cp.async.commit_group;");
                va = *(const float4*)(hsrc + (size_t)(r0 + a_row) * 512 + kn + a_q * 4);
                asm volatile("cp.async.wait_group 1;");   // B(kc) landed
            } else {
                asm volatile("cp.async.wait_group 0;");
            }

            // ---- MMAs on current buffer ----
#pragma unroll
            for (int s = 0; s < 2; ++s) {
                int kb = s * 16;
                uint32_t ah[4], al[4];
                {
                    int arow = wm * 16 + g8 + ((m4 & 1) << 3);
                    int acol = kb + ((m4 & 2) << 2);
                    uint32_t ao = cbuf + arow * 80 + acol * 2;
                    ldsm4(ah, ao + S_AHI);
                    ldsm4(al, ao + S_ALO);
                }
#pragma unroll
                for (int jp = 0; jp < 4; ++jp) {
                    int brow = wn * 64 + jp * 16 + g8 + ((m4 & 2) << 2);
                    int bcol = kb + ((m4 & 1) << 3);
                    uint32_t bo = cbuf + brow * 80 + bcol * 2;
                    uint32_t bh[4], bl[4];
                    ldsm4(bh, bo + S_BHI);
                    ldsm4(bl, bo + S_BLO);
#pragma unroll
                    for (int hh = 0; hh < 2; ++hh) {
                        int j = jp * 2 + hh;
                        mma16816(acc[j], ah, bh[2 * hh], bh[2 * hh + 1]);
                        mma16816(acc[j], ah, bl[2 * hh], bl[2 * hh + 1]);
                        mma16816(acc[j], al, bh[2 * hh], bh[2 * hh + 1]);
                    }
                }
            }

            // ---- A(kc+1) split + STS into other buffer ----
            if (kc < 15) {
                uint32_t h0, l0, h1, l1;
                split2(va.x, va.y, h0, l0);
                split2(va.z, va.w, h1, l1);
                uint32_t dsto = (uint32_t)(a_row * 80 + a_q * 8);
                *(uint2*)(smem + (nbuf - sb) + S_AHI + dsto) = make_uint2(h0, h1);
                *(uint2*)(smem + (nbuf - sb) + S_ALO + dsto) = make_uint2(l0, l1);
            }
        }

        // ===== LayerNorm stats =====
        float s1[2] = {0.f, 0.f}, s2a[2] = {0.f, 0.f};
#pragma unroll
        for (int j = 0; j < 8; ++j) {
            float2 b1v = *(const float2*)(b1 + wn * 64 + 8 * j + 2 * t);
            float v0 = acc[j][0] + b1v.x, v1 = acc[j][1] + b1v.y;
            float v2 = acc[j][2] + b1v.x, v3 = acc[j][3] + b1v.y;
            s1[0] += v0 + v1;  s2a[0] += v0 * v0 + v1 * v1;
            s1[1] += v2 + v3;  s2a[1] += v2 * v2 + v3 * v3;
        }
#pragma unroll
        for (int rp = 0; rp < 2; ++rp) {
            s1[rp]  += __shfl_xor_sync(0xFFFFFFFFu, s1[rp], 1);
            s1[rp]  += __shfl_xor_sync(0xFFFFFFFFu, s1[rp], 2);
            s2a[rp] += __shfl_xor_sync(0xFFFFFFFFu, s2a[rp], 1);
            s2a[rp] += __shfl_xor_sync(0xFFFFFFFFu, s2a[rp], 2);
        }
        if (t == 0) {
#pragma unroll
            for (int rp = 0; rp < 2; ++rp) {
                int row = wm * 16 + g + 8 * rp;
                stats[row * 8 + wn * 2]     = s1[rp];
                stats[row * 8 + wn * 2 + 1] = s2a[rp];
            }
        }
        __syncthreads();
        float mu[2], rs[2];
#pragma unroll
        for (int rp = 0; rp < 2; ++rp) {
            int row = wm * 16 + g + 8 * rp;
            float S  = stats[row * 8] + stats[row * 8 + 2] + stats[row * 8 + 4] + stats[row * 8 + 6];
            float S2 = stats[row * 8 + 1] + stats[row * 8 + 3] + stats[row * 8 + 5] + stats[row * 8 + 7];
            float m = S * (1.f / 256.f);
            float var = S2 * (1.f / 256.f) - m * m;
            mu[rp] = m;
            rs[rp] = rsqrtf(var + 1e-5f);
        }
        __syncthreads();   // staging reads fully done before X overwrites region

        // ===== GELU + pack -> x slabs (hi/lo, SW128 swizzled 128B rows) =====
        const int xbase = OFF_X + wn * 16384;
#pragma unroll
        for (int j = 0; j < 8; ++j) {
            int cg = wn * 64 + 8 * j + 2 * t;
            float2 b1v = *(const float2*)(b1 + cg);
            float2 lgv = *(const float2*)(lg + cg);
            float2 lbv = *(const float2*)(lb + cg);
            int rowt = wm * 16 + g;
            {
                float y0 = (acc[j][0] + b1v.x - mu[0]) * rs[0] * lgv.x + lbv.x;
                float y1 = (acc[j][1] + b1v.y - mu[0]) * rs[0] * lgv.y + lbv.y;
                float g0 = 0.5f * y0 * (1.f + erff(y0 * 0.70710678118654752f));
                float g1 = 0.5f * y1 * (1.f + erff(y1 * 0.70710678118654752f));
                uint32_t hh, ll;
                split2(g0, g1, hh, ll);
                uint32_t off = (uint32_t)(rowt * 128 + (8 * j + 2 * t) * 2);
                *(uint32_t*)(smem + xbase + SW(off))       = hh;
                *(uint32_t*)(smem + xbase + XLO + SW(off)) = ll;
            }
            {
                float y0 = (acc[j][2] + b1v.x - mu[1]) * rs[1] * lgv.x + lbv.x;
                float y1 = (acc[j][3] + b1v.y - mu[1]) * rs[1] * lgv.y + lbv.y;
                float g0 = 0.5f * y0 * (1.f + erff(y0 * 0.70710678118654752f));
                float g1 = 0.5f * y1 * (1.f + erff(y1 * 0.70710678118654752f));
                uint32_t hh, ll;
                split2(g0, g1, hh, ll);
                uint32_t off = (uint32_t)((rowt + 8) * 128 + (8 * j + 2 * t) * 2);
                *(uint32_t*)(smem + xbase + SW(off))       = hh;
                *(uint32_t*)(smem + xbase + XLO + SW(off)) = ll;
            }
        }
        // init mbuf[p] with bias b2
        for (int i = tid; i < 8192; i += NT) {
            int row = i >> 6, c = i & 63;
            mbuf[p * 8320 + row * 65 + c] = b2[c];
        }
        __syncthreads();

        // ===== GEMM2: split-K, warp computes 16x64 partial over k = wn*64..+64 =====
        float a2[8][4];
#pragma unroll
        for (int j = 0; j < 8; ++j)
#pragma unroll
            for (int q = 0; q < 4; ++q) a2[j][q] = 0.f;

#pragma unroll
        for (int s = 0; s < 4; ++s) {
            uint32_t ah[4], al[4];
            {
                int arow = wm * 16 + g8 + ((m4 & 1) << 3);
                int lcol = s * 16 + ((m4 & 2) << 2);
                uint32_t off = SW((uint32_t)(arow * 128 + lcol * 2));
                ldsm4(ah, sb + xbase + off);
                ldsm4(al, sb + xbase + XLO + off);
            }
            int kp0 = wn * 32 + 8 * s + t;
#pragma unroll
            for (int j2 = 0; j2 < 8; ++j2) {
                int nrow = 8 * j2 + g;
                uint32_t b0h = w2h[nrow * 128 + kp0], b1h = w2h[nrow * 128 + kp0 + 4];
                uint32_t b0l = w2l[nrow * 128 + kp0], b1l = w2l[nrow * 128 + kp0 + 4];
                mma16816(a2[j2], ah, b0h, b1h);
                mma16816(a2[j2], ah, b0l, b1l);
                mma16816(a2[j2], al, b0h, b1h);
            }
        }
        float* mb = mbuf + p * 8320;
        {
            int rowt = wm * 16 + g;
#pragma unroll
            for (int j2 = 0; j2 < 8; ++j2) {
                int c0 = 8 * j2 + 2 * t;
                atomicAdd(&mb[rowt * 65 + c0],           a2[j2][0]);
                atomicAdd(&mb[rowt * 65 + c0 + 1],       a2[j2][1]);
                atomicAdd(&mb[(rowt + 8) * 65 + c0],     a2[j2][2]);
                atomicAdd(&mb[(rowt + 8) * 65 + c0 + 1], a2[j2][3]);
            }
        }
        __syncthreads();
    }

    // ===== Cayley contraction with gw -> P[128,64] =====
    float gwr[8];
#pragma unroll
    for (int n = 0; n < 8; ++n) gwr[n] = gw[n];
    const int MASKc[8] = {0, 1, 2, 4, 3, 5, 6, 7};
    float* pbuf = (float*)(smem + OFF_X);   // [128][65]
    {
        int row = tid & 127;
        int k = tid >> 7;       // 0..7, one k per thread
        const float* mp = mbuf + row * 65;
        const float* mv = mbuf + 8320 + row * 65;
        float mpv[8], mvv[8];
#pragma unroll
        for (int i = 0; i < 8; ++i) { mpv[i] = mp[k * 8 + i]; mvv[i] = mv[k * 8 + i]; }
        float Q[8];
#pragma unroll
        for (int m = 0; m < 8; ++m) {
            float q = 0.f;
#pragma unroll
            for (int j = 0; j < 8; ++j) {
                int am = MASKc[m], bm = MASKc[j];
                int sw = __popc((am >> 1) & bm) + __popc((am >> 2) & bm);
                float sg = (sw & 1) ? -1.f : 1.f;
                q += sg * gwr[MASKc[am ^ bm]] * mvv[j];
            }
            Q[m] = q;
        }
#pragma unroll
        for (int j = 0; j < 8; ++j) {
            float pv = 0.f;
#pragma unroll
            for (int i = 0; i < 8; ++i) {
                int am = MASKc[i], bm = MASKc[j];
                int sw = __popc((am >> 1) & bm) + __popc((am >> 2) & bm);
                float sg = (sw & 1) ? -1.f : 1.f;
                pv += sg * mpv[i] * Q[MASKc[am ^ bm]];
            }
            pbuf[row * 65 + k * 8 + j] = pv;
        }
    }
    __syncthreads();

    // ===== out[128,95] = P[128,64] @ Tbuf[64,95] =====
    {
        const int ty = tid >> 4;   // 0..63, 2 rows each
        const int tx = tid & 15;   // cols tx + 16j, j<6
        float acc3[2][6];
#pragma unroll
        for (int i = 0; i < 2; ++i)
#pragma unroll
            for (int j = 0; j < 6; ++j) acc3[i][j] = 0.f;
#pragma unroll 8
        for (int k = 0; k < 64; ++k) {
            float a[2], b[6];
#pragma unroll
            for (int i = 0; i < 2; ++i) a[i] = pbuf[(ty * 2 + i) * 65 + k];
#pragma unroll
            for (int j = 0; j < 6; ++j) {
                int col = tx + 16 * j;
                b[j] = (col < 95) ? Tbuf[k * 97 + col] : 0.f;
            }
#pragma unroll
            for (int i = 0; i < 2; ++i)
#pragma unroll
                for (int j = 0; j < 6; ++j) acc3[i][j] += a[i] * b[j];
        }
#pragma unroll
        for (int i = 0; i < 2; ++i)
#pragma unroll
            for (int j = 0; j < 6; ++j) {
                int col = tx + 16 * j;
                if (col < 95)
                    out[(size_t)(r0 + ty * 2 + i) * 95 + col] = acc3[i][j];
            }
    }
}

extern "C" void kernel_launch(void* const* d_in, const int* in_sizes, int n_in,
                              void* d_out, int out_size) {
    const float* h_perp = (const float*)d_in[0];
    const float* h_vuln = (const float*)d_in[1];
    const float* Wp1 = (const float*)d_in[2];
    const float* bp1 = (const float*)d_in[3];
    const float* lgp = (const float*)d_in[4];
    const float* lbp = (const float*)d_in[5];
    const float* Wp2 = (const float*)d_in[6];
    const float* bp2 = (const float*)d_in[7];
    const float* Wv1 = (const float*)d_in[8];
    const float* bv1 = (const float*)d_in[9];
    const float* lgv = (const float*)d_in[10];
    const float* lbv = (const float*)d_in[11];
    const float* Wv2 = (const float*)d_in[12];
    const float* bv2 = (const float*)d_in[13];
    const float* Tm  = (const float*)d_in[14];
    const float* gw  = (const float*)d_in[15];
    float* out = (float*)d_out;

    int B = in_sizes[0] / 512;   // 16384
    int grid = B / TB;           // 128

    prep_kernel<<<(65536 + 8192 + 255) / 256, 256>>>(Wp1, Wv1, Wp2, Wv2);

    cudaFuncSetAttribute(clifford_mma_kernel,
                         cudaFuncAttributeMaxDynamicSharedMemorySize, SMEM_BYTES);
    clifford_mma_kernel<<<grid, NT, SMEM_BYTES>>>(
        h_perp, h_vuln, bp1, lgp, lbp, bp2, bv1, lgv, lbv, bv2, Tm, gw, out);
}

// round 8
// speedup vs baseline: 1.2374x; 1.2374x over previous
#include <cuda_runtime.h>
#include <cuda_bf16.h>
#include <cstdint>
#include <math.h>

// ----------------------------------------------------------------------------
// B=16384, D=512, H=256, R=95, KJ=64. TB=128 rows/CTA, 512 threads (16 warps,
// 4m x 4n warp grid, warp tile 32x64), 1 CTA/SM. mma.sync m16n8k16 bf16,
// hi/lo split (3 products) re-scheduled in passes to break accumulator RAW
// chains (dep distance 1 -> 8). Arithmetic order per accumulator unchanged.
// ----------------------------------------------------------------------------

#define TB 128
#define NT 512

// smem byte offsets
#define OFF_A1   0        // GEMM1 A staging hi [128][144] (+lo at +18432), overlaps X
#define A1LO     18432
#define OFF_B1   36864    // GEMM1 B staging hi [256][144] (+lo at +36864)
#define B1LO     36864
#define OFF_X    0        // x slabs: hi [4 wn][128][128B]=65536, lo at +65536
#define XLO      65536
#define OFF_MB   131072   // mbuf [2][128][65] f32 = 66560
#define OFF_TB   197632   // Tbuf [64][97] f32 = 24832
#define OFF_ST   222464   // stats [128][8] f32 = 4096
#define SMEM_BYTES 226560

#define SW(x) ((x) ^ (((x) >> 3) & 0x70))

static __device__ __forceinline__ uint32_t smem_u32(const void* p) {
    uint32_t a;
    asm("{ .reg .u64 t; cvta.to.shared.u64 t, %1; cvt.u32.u64 %0, t; }" : "=r"(a) : "l"(p));
    return a;
}

static __device__ __forceinline__ void ldsm4(uint32_t* r, uint32_t addr) {
    asm volatile("ldmatrix.sync.aligned.m8n8.x4.shared.b16 {%0,%1,%2,%3}, [%4];"
                 : "=r"(r[0]), "=r"(r[1]), "=r"(r[2]), "=r"(r[3]) : "r"(addr));
}

static __device__ __forceinline__ void mma16816(float* c, const uint32_t* a,
                                                uint32_t b0, uint32_t b1) {
    asm volatile(
        "mma.sync.aligned.m16n8k16.row.col.f32.bf16.bf16.f32 "
        "{%0,%1,%2,%3}, {%4,%5,%6,%7}, {%8,%9}, {%0,%1,%2,%3};"
        : "+f"(c[0]), "+f"(c[1]), "+f"(c[2]), "+f"(c[3])
        : "r"(a[0]), "r"(a[1]), "r"(a[2]), "r"(a[3]), "r"(b0), "r"(b1));
}

// hi/lo bf16 split of a float pair, packed (elem0 in low half)
static __device__ __forceinline__ void split2(float a0, float a1, uint32_t& hi, uint32_t& lo) {
    __nv_bfloat16 h0 = __float2bfloat16_rn(a0), h1 = __float2bfloat16_rn(a1);
    float f0 = __bfloat162float(h0), f1 = __bfloat162float(h1);
    __nv_bfloat16 l0 = __float2bfloat16_rn(a0 - f0), l1 = __float2bfloat16_rn(a1 - f1);
    hi = ((uint32_t)__bfloat16_as_ushort(h1) << 16) | (uint32_t)__bfloat16_as_ushort(h0);
    lo = ((uint32_t)__bfloat16_as_ushort(l1) << 16) | (uint32_t)__bfloat16_as_ushort(l0);
}

// weight scratch: W1^T u32[n=256][kp=256], W2^T u32[n=64][kp=128]  (kp = k/2 pairs)
__device__ __align__(16) uint32_t g_w1t_hi[2][256 * 256];
__device__ __align__(16) uint32_t g_w1t_lo[2][256 * 256];
__device__ __align__(16) uint32_t g_w2t_hi[2][64 * 128];
__device__ __align__(16) uint32_t g_w2t_lo[2][64 * 128];

__global__ void prep_kernel(const float* __restrict__ Wp1, const float* __restrict__ Wv1,
                            const float* __restrict__ Wp2, const float* __restrict__ Wv2) {
    int idx = blockIdx.x * blockDim.x + threadIdx.x;
    if (idx < 65536) {
        int n = idx >> 8, kp = idx & 255;
#pragma unroll
        for (int p = 0; p < 2; ++p) {
            const float* W1 = p ? Wv1 : Wp1;
            float a0 = W1[(2 * kp) * 256 + n];
            float a1 = W1[(2 * kp + 1) * 256 + n];
            uint32_t hi, lo;
            split2(a0, a1, hi, lo);
            g_w1t_hi[p][n * 256 + kp] = hi;
            g_w1t_lo[p][n * 256 + kp] = lo;
        }
    } else if (idx < 65536 + 8192) {
        int j = idx - 65536;
        int n = j >> 7, kp = j & 127;
#pragma unroll
        for (int p = 0; p < 2; ++p) {
            const float* W2 = p ? Wv2 : Wp2;
            float a0 = W2[(2 * kp) * 64 + n];
            float a1 = W2[(2 * kp + 1) * 64 + n];
            uint32_t hi, lo;
            split2(a0, a1, hi, lo);
            g_w2t_hi[p][n * 128 + kp] = hi;
            g_w2t_lo[p][n * 128 + kp] = lo;
        }
    }
}

__global__ __launch_bounds__(NT, 1)
void clifford_mma_kernel(
    const float* __restrict__ h_perp, const float* __restrict__ h_vuln,
    const float* __restrict__ bp1, const float* __restrict__ lgp,
    const float* __restrict__ lbp, const float* __restrict__ bp2,
    const float* __restrict__ bv1, const float* __restrict__ lgv,
    const float* __restrict__ lbv, const float* __restrict__ bv2,
    const float* __restrict__ Tm, const float* __restrict__ gw,
    float* __restrict__ out)
{
    extern __shared__ char smem[];
    const uint32_t sb = smem_u32(smem);
    const int tid = threadIdx.x;
    const int lane = tid & 31;
    const int wid = tid >> 5;
    const int wm = wid & 3;       // m-block: rows wm*32..+32
    const int wn = wid >> 2;      // n-block: cols wn*64..+64
    const int g = lane >> 2, t = lane & 3;
    const int g8 = lane & 7, m4 = lane >> 3;
    const int r0 = blockIdx.x * TB;

    float* mbuf  = (float*)(smem + OFF_MB);
    float* Tbuf  = (float*)(smem + OFF_TB);
    float* stats = (float*)(smem + OFF_ST);

    // stage T^T scaled by 1/8
    for (int i = tid; i < 95 * 64; i += NT) {
        int r = i >> 6, kj = i & 63;
        Tbuf[kj * 97 + r] = Tm[i] * 0.125f;
    }

    for (int p = 0; p < 2; ++p) {
        const float* hsrc = p ? h_vuln : h_perp;
        const uint32_t* w1h = g_w1t_hi[p];
        const uint32_t* w1l = g_w1t_lo[p];
        const uint32_t* w2h = g_w2t_hi[p];
        const uint32_t* w2l = g_w2t_lo[p];
        const float* b1 = p ? bv1 : bp1;
        const float* lg = p ? lgv : lgp;
        const float* lb = p ? lbv : lbp;
        const float* b2 = p ? bv2 : bp2;

        // ===== GEMM1: acc[128,256] = h @ W1, warp tile 32x64 =====
        float acc[2][8][4];
#pragma unroll
        for (int mi = 0; mi < 2; ++mi)
#pragma unroll
            for (int j = 0; j < 8; ++j)
#pragma unroll
                for (int q = 0; q < 4; ++q) acc[mi][j][q] = 0.f;

        for (int kk = 0; kk < 512; kk += 64) {
            __syncthreads();
            // A staging: 128x64 fp32 -> bf16 hi/lo, row stride 144B
#pragma unroll
            for (int z = 0; z < 4; ++z) {
                int i = tid + z * NT;
                int row = i >> 4, gq = i & 15;
                float4 v = *(const float4*)(hsrc + (size_t)(r0 + row) * 512 + kk + gq * 4);
                uint32_t h0, l0, h1, l1;
                split2(v.x, v.y, h0, l0);
                split2(v.z, v.w, h1, l1);
                char* base = smem + OFF_A1 + row * 144 + gq * 8;
                *(uint2*)(base)        = make_uint2(h0, h1);
                *(uint2*)(base + A1LO) = make_uint2(l0, l1);
            }
            // B staging: copy w1t chunk 256x(32 u32), row stride 144B
#pragma unroll
            for (int z = 0; z < 4; ++z) {
                int i = tid + z * NT;
                int row = i >> 3, q = i & 7;
                uint4 vh = *(const uint4*)(w1h + row * 256 + (kk >> 1) + q * 4);
                uint4 vl = *(const uint4*)(w1l + row * 256 + (kk >> 1) + q * 4);
                char* base = smem + OFF_B1 + row * 144 + q * 16;
                *(uint4*)(base)        = vh;
                *(uint4*)(base + B1LO) = vl;
            }
            __syncthreads();

            for (int s = 0; s < 4; ++s) {
                int kb = s * 16;
                uint32_t ah[2][4], al[2][4];
#pragma unroll
                for (int mi = 0; mi < 2; ++mi) {
                    int arow = wm * 32 + mi * 16 + g8 + ((m4 & 1) << 3);
                    int acol = kb + ((m4 & 2) << 2);
                    uint32_t ao = sb + OFF_A1 + arow * 144 + acol * 2;
                    ldsm4(ah[mi], ao);
                    ldsm4(al[mi], ao + A1LO);
                }
                // two halves of the 64-wide n tile; per half, hold B frags and
                // sweep products in passes to break accumulator RAW chains
#pragma unroll
                for (int jh = 0; jh < 2; ++jh) {
                    uint32_t bh[2][4], bl[2][4];
#pragma unroll
                    for (int j2 = 0; j2 < 2; ++j2) {
                        int jp = jh * 2 + j2;
                        int brow = wn * 64 + jp * 16 + g8 + ((m4 & 2) << 2);
                        int bcol = kb + ((m4 & 1) << 3);
                        uint32_t bo = sb + OFF_B1 + brow * 144 + bcol * 2;
                        ldsm4(bh[j2], bo);
                        ldsm4(bl[j2], bo + B1LO);
                    }
                    // pass 0: hi*hi (8 independent accumulators)
#pragma unroll
                    for (int j2 = 0; j2 < 2; ++j2)
#pragma unroll
                        for (int hh = 0; hh < 2; ++hh)
#pragma unroll
                            for (int mi = 0; mi < 2; ++mi)
                                mma16816(acc[mi][(jh * 2 + j2) * 2 + hh], ah[mi],
                                         bh[j2][2 * hh], bh[j2][2 * hh + 1]);
                    // pass 1: hi*lo
#pragma unroll
                    for (int j2 = 0; j2 < 2; ++j2)
#pragma unroll
                        for (int hh = 0; hh < 2; ++hh)
#pragma unroll
                            for (int mi = 0; mi < 2; ++mi)
                                mma16816(acc[mi][(jh * 2 + j2) * 2 + hh], ah[mi],
                                         bl[j2][2 * hh], bl[j2][2 * hh + 1]);
                    // pass 2: lo*hi
#pragma unroll
                    for (int j2 = 0; j2 < 2; ++j2)
#pragma unroll
                        for (int hh = 0; hh < 2; ++hh)
#pragma unroll
                            for (int mi = 0; mi < 2; ++mi)
                                mma16816(acc[mi][(jh * 2 + j2) * 2 + hh], al[mi],
                                         bh[j2][2 * hh], bh[j2][2 * hh + 1]);
                }
            }
        }

        // ===== LayerNorm stats =====
        float s1[2][2] = {{0.f, 0.f}, {0.f, 0.f}};
        float s2a[2][2] = {{0.f, 0.f}, {0.f, 0.f}};
#pragma unroll
        for (int j = 0; j < 8; ++j) {
            float2 b1v = *(const float2*)(b1 + wn * 64 + 8 * j + 2 * t);
#pragma unroll
            for (int mi = 0; mi < 2; ++mi) {
                float v0 = acc[mi][j][0] + b1v.x, v1 = acc[mi][j][1] + b1v.y;
                float v2 = acc[mi][j][2] + b1v.x, v3 = acc[mi][j][3] + b1v.y;
                s1[mi][0] += v0 + v1;  s2a[mi][0] += v0 * v0 + v1 * v1;
                s1[mi][1] += v2 + v3;  s2a[mi][1] += v2 * v2 + v3 * v3;
            }
        }
#pragma unroll
        for (int mi = 0; mi < 2; ++mi)
#pragma unroll
            for (int rp = 0; rp < 2; ++rp) {
                s1[mi][rp]  += __shfl_xor_sync(0xFFFFFFFFu, s1[mi][rp], 1);
                s1[mi][rp]  += __shfl_xor_sync(0xFFFFFFFFu, s1[mi][rp], 2);
                s2a[mi][rp] += __shfl_xor_sync(0xFFFFFFFFu, s2a[mi][rp], 1);
                s2a[mi][rp] += __shfl_xor_sync(0xFFFFFFFFu, s2a[mi][rp], 2);
            }
        if (t == 0) {
#pragma unroll
            for (int mi = 0; mi < 2; ++mi)
#pragma unroll
                for (int rp = 0; rp < 2; ++rp) {
                    int row = wm * 32 + mi * 16 + g + 8 * rp;
                    stats[row * 8 + wn * 2]     = s1[mi][rp];
                    stats[row * 8 + wn * 2 + 1] = s2a[mi][rp];
                }
        }
        __syncthreads();
        float mu[2][2], rs[2][2];
#pragma unroll
        for (int mi = 0; mi < 2; ++mi)
#pragma unroll
            for (int rp = 0; rp < 2; ++rp) {
                int row = wm * 32 + mi * 16 + g + 8 * rp;
                float S  = stats[row * 8] + stats[row * 8 + 2] + stats[row * 8 + 4] + stats[row * 8 + 6];
                float S2 = stats[row * 8 + 1] + stats[row * 8 + 3] + stats[row * 8 + 5] + stats[row * 8 + 7];
                float m = S * (1.f / 256.f);
                float var = S2 * (1.f / 256.f) - m * m;
                mu[mi][rp] = m;
                rs[mi][rp] = rsqrtf(var + 1e-5f);
            }
        __syncthreads();   // staging reads done before X overwrites region

        // ===== GELU + pack -> x slabs (hi/lo, SW128 swizzled 128B rows) =====
        const int xbase = OFF_X + wn * 16384;
#pragma unroll
        for (int j = 0; j < 8; ++j) {
            int cg = wn * 64 + 8 * j + 2 * t;
            float2 b1v = *(const float2*)(b1 + cg);
            float2 lgv = *(const float2*)(lg + cg);
            float2 lbv = *(const float2*)(lb + cg);
#pragma unroll
            for (int mi = 0; mi < 2; ++mi) {
                int rowt = wm * 32 + mi * 16 + g;
                {
                    float y0 = (acc[mi][j][0] + b1v.x - mu[mi][0]) * rs[mi][0] * lgv.x + lbv.x;
                    float y1 = (acc[mi][j][1] + b1v.y - mu[mi][0]) * rs[mi][0] * lgv.y + lbv.y;
                    float g0 = 0.5f * y0 * (1.f + erff(y0 * 0.70710678118654752f));
                    float g1 = 0.5f * y1 * (1.f + erff(y1 * 0.70710678118654752f));
                    uint32_t hh, ll;
                    split2(g0, g1, hh, ll);
                    uint32_t off = (uint32_t)(rowt * 128 + (8 * j + 2 * t) * 2);
                    *(uint32_t*)(smem + xbase + SW(off))       = hh;
                    *(uint32_t*)(smem + xbase + XLO + SW(off)) = ll;
                }
                {
                    float y0 = (acc[mi][j][2] + b1v.x - mu[mi][1]) * rs[mi][1] * lgv.x + lbv.x;
                    float y1 = (acc[mi][j][3] + b1v.y - mu[mi][1]) * rs[mi][1] * lgv.y + lbv.y;
                    float g0 = 0.5f * y0 * (1.f + erff(y0 * 0.70710678118654752f));
                    float g1 = 0.5f * y1 * (1.f + erff(y1 * 0.70710678118654752f));
                    uint32_t hh, ll;
                    split2(g0, g1, hh, ll);
                    uint32_t off = (uint32_t)((rowt + 8) * 128 + (8 * j + 2 * t) * 2);
                    *(uint32_t*)(smem + xbase + SW(off))       = hh;
                    *(uint32_t*)(smem + xbase + XLO + SW(off)) = ll;
                }
            }
        }
        // init mbuf[p] with bias b2
        for (int i = tid; i < 8192; i += NT) {
            int row = i >> 6, c = i & 63;
            mbuf[p * 8320 + row * 65 + c] = b2[c];
        }
        __syncthreads();

        // ===== GEMM2: split-K, warp computes 32x64 partial over k = wn*64..+64 =====
        float a2[2][8][4];
#pragma unroll
        for (int mi = 0; mi < 2; ++mi)
#pragma unroll
            for (int j = 0; j < 8; ++j)
#pragma unroll
                for (int q = 0; q < 4; ++q) a2[mi][j][q] = 0.f;

#pragma unroll
        for (int s = 0; s < 4; ++s) {
            uint32_t ah[2][4], al[2][4];
#pragma unroll
            for (int mi = 0; mi < 2; ++mi) {
                int arow = wm * 32 + mi * 16 + g8 + ((m4 & 1) << 3);
                int lcol = s * 16 + ((m4 & 2) << 2);
                uint32_t off = SW((uint32_t)(arow * 128 + lcol * 2));
                ldsm4(ah[mi], sb + xbase + off);
                ldsm4(al[mi], sb + xbase + XLO + off);
            }
            int kp0 = wn * 32 + 8 * s + t;
#pragma unroll
            for (int j2 = 0; j2 < 8; ++j2) {
                int nrow = 8 * j2 + g;
                uint32_t b0h = w2h[nrow * 128 + kp0], b1h = w2h[nrow * 128 + kp0 + 4];
                uint32_t b0l = w2l[nrow * 128 + kp0], b1l = w2l[nrow * 128 + kp0 + 4];
#pragma unroll
                for (int mi = 0; mi < 2; ++mi) {
                    mma16816(a2[mi][j2], ah[mi], b0h, b1h);
                    mma16816(a2[mi][j2], ah[mi], b0l, b1l);
                    mma16816(a2[mi][j2], al[mi], b0h, b1h);
                }
            }
        }
        float* mb = mbuf + p * 8320;
#pragma unroll
        for (int mi = 0; mi < 2; ++mi) {
            int rowt = wm * 32 + mi * 16 + g;
#pragma unroll
            for (int j2 = 0; j2 < 8; ++j2) {
                int c0 = 8 * j2 + 2 * t;
                atomicAdd(&mb[rowt * 65 + c0],           a2[mi][j2][0]);
                atomicAdd(&mb[rowt * 65 + c0 + 1],       a2[mi][j2][1]);
                atomicAdd(&mb[(rowt + 8) * 65 + c0],     a2[mi][j2][2]);
                atomicAdd(&mb[(rowt + 8) * 65 + c0 + 1], a2[mi][j2][3]);
            }
        }
        __syncthreads();
    }

    // ===== Cayley contraction with gw -> P[128,64] =====
    float gwr[8];
#pragma unroll
    for (int n = 0; n < 8; ++n) gwr[n] = gw[n];
    const int MASKc[8] = {0, 1, 2, 4, 3, 5, 6, 7};
    float* pbuf = (float*)(smem + OFF_X);   // [128][65]
    {
        int row = tid & 127;
        int kb2 = (tid >> 7) * 2;
        const float* mp = mbuf + row * 65;
        const float* mv = mbuf + 8320 + row * 65;
#pragma unroll
        for (int kk2 = 0; kk2 < 2; ++kk2) {
            int k = kb2 + kk2;
            float mpv[8], mvv[8];
#pragma unroll
            for (int i = 0; i < 8; ++i) { mpv[i] = mp[k * 8 + i]; mvv[i] = mv[k * 8 + i]; }
            float Q[8];
#pragma unroll
            for (int m = 0; m < 8; ++m) {
                float q = 0.f;
#pragma unroll
                for (int j = 0; j < 8; ++j) {
                    int am = MASKc[m], bm = MASKc[j];
                    int sw = __popc((am >> 1) & bm) + __popc((am >> 2) & bm);
                    float sg = (sw & 1) ? -1.f : 1.f;
                    q += sg * gwr[MASKc[am ^ bm]] * mvv[j];
                }
                Q[m] = q;
            }
#pragma unroll
            for (int j = 0; j < 8; ++j) {
                float pv = 0.f;
#pragma unroll
                for (int i = 0; i < 8; ++i) {
                    int am = MASKc[i], bm = MASKc[j];
                    int sw = __popc((am >> 1) & bm) + __popc((am >> 2) & bm);
                    float sg = (sw & 1) ? -1.f : 1.f;
                    pv += sg * mpv[i] * Q[MASKc[am ^ bm]];
                }
                pbuf[row * 65 + k * 8 + j] = pv;
            }
        }
    }
    __syncthreads();

    // ===== out[128,95] = P[128,64] @ Tbuf[64,95] =====
    {
        const int ty = tid >> 4;   // 0..31, 4 rows each
        const int tx = tid & 15;   // cols tx + 16j, j<6
        float acc3[4][6];
#pragma unroll
        for (int i = 0; i < 4; ++i)
#pragma unroll
            for (int j = 0; j < 6; ++j) acc3[i][j] = 0.f;
#pragma unroll 8
        for (int k = 0; k < 64; ++k) {
            float a[4], b[6];
#pragma unroll
            for (int i = 0; i < 4; ++i) a[i] = pbuf[(ty * 4 + i) * 65 + k];
#pragma unroll
            for (int j = 0; j < 6; ++j) {
                int col = tx + 16 * j;
                b[j] = (col < 95) ? Tbuf[k * 97 + col] : 0.f;
            }
#pragma unroll
            for (int i = 0; i < 4; ++i)
#pragma unroll
                for (int j = 0; j < 6; ++j) acc3[i][j] += a[i] * b[j];
        }
#pragma unroll
        for (int i = 0; i < 4; ++i)
#pragma unroll
            for (int j = 0; j < 6; ++j) {
                int col = tx + 16 * j;
                if (col < 95)
                    out[(size_t)(r0 + ty * 4 + i) * 95 + col] = acc3[i][j];
            }
    }
}

extern "C" void kernel_launch(void* const* d_in, const int* in_sizes, int n_in,
                              void* d_out, int out_size) {
    const float* h_perp = (const float*)d_in[0];
    const float* h_vuln = (const float*)d_in[1];
    const float* Wp1 = (const float*)d_in[2];
    const float* bp1 = (const float*)d_in[3];
    const float* lgp = (const float*)d_in[4];
    const float* lbp = (const float*)d_in[5];
    const float* Wp2 = (const float*)d_in[6];
    const float* bp2 = (const float*)d_in[7];
    const float* Wv1 = (const float*)d_in[8];
    const float* bv1 = (const float*)d_in[9];
    const float* lgv = (const float*)d_in[10];
    const float* lbv = (const float*)d_in[11];
    const float* Wv2 = (const float*)d_in[12];
    const float* bv2 = (const float*)d_in[13];
    const float* Tm  = (const float*)d_in[14];
    const float* gw  = (const float*)d_in[15];
    float* out = (float*)d_out;

    int B = in_sizes[0] / 512;   // 16384
    int grid = B / TB;           // 128

    prep_kernel<<<(65536 + 8192 + 255) / 256, 256>>>(Wp1, Wv1, Wp2, Wv2);

    cudaFuncSetAttribute(clifford_mma_kernel,
                         cudaFuncAttributeMaxDynamicSharedMemorySize, SMEM_BYTES);
    clifford_mma_kernel<<<grid, NT, SMEM_BYTES>>>(
        h_perp, h_vuln, bp1, lgp, lbp, bp2, bv1, lgv, lbv, bv2, Tm, gw, out);
}

// round 10
// speedup vs baseline: 1.3886x; 1.1221x over previous
#include <cuda_runtime.h>
#include <cuda_bf16.h>
#include <cstdint>
#include <math.h>

// ----------------------------------------------------------------------------
// B=16384, D=512, H=256, R=95, KJ=64. TB=128 rows/CTA, 512 threads (16 warps),
// 1 CTA/SM. mma.sync m16n8k16 bf16, hi/lo split (3 products, pass-scheduled).
// R9: tensor-core T-GEMM, atomic-free GEMM2 (8m x 2n), packed split2.
// ----------------------------------------------------------------------------

#define TB 128
#define NT 512

// smem byte offsets
#define OFF_A1   0        // GEMM1 A staging hi [128][144] (+lo at +18432), overlaps X
#define A1LO     18432
#define OFF_B1   36864    // GEMM1 B staging hi [256][144] (+lo at +36864)
#define B1LO     36864
#define OFF_X    0        // x slabs: hi [4 slab][128][128B]=65536, lo at +65536
#define XLO      65536
#define OFF_MB   131072   // mbuf [2][128][65] f32 = 66560
#define OFF_ST   222464   // stats [128][8] f32 = 4096
#define SMEM_BYTES 226560
// P slabs (post-GEMM2, X region dead): hi @ OFF_X, lo @ OFF_X+16384

#define SW(x) ((x) ^ (((x) >> 3) & 0x70))

static __device__ __forceinline__ uint32_t smem_u32(const void* p) {
    uint32_t a;
    asm("{ .reg .u64 t; cvta.to.shared.u64 t, %1; cvt.u32.u64 %0, t; }" : "=r"(a) : "l"(p));
    return a;
}

static __device__ __forceinline__ void ldsm4(uint32_t* r, uint32_t addr) {
    asm volatile("ldmatrix.sync.aligned.m8n8.x4.shared.b16 {%0,%1,%2,%3}, [%4];"
                 : "=r"(r[0]), "=r"(r[1]), "=r"(r[2]), "=r"(r[3]) : "r"(addr));
}

static __device__ __forceinline__ void mma16816(float* c, const uint32_t* a,
                                                uint32_t b0, uint32_t b1) {
    asm volatile(
        "mma.sync.aligned.m16n8k16.row.col.f32.bf16.bf16.f32 "
        "{%0,%1,%2,%3}, {%4,%5,%6,%7}, {%8,%9}, {%0,%1,%2,%3};"
        : "+f"(c[0]), "+f"(c[1]), "+f"(c[2]), "+f"(c[3])
        : "r"(a[0]), "r"(a[1]), "r"(a[2]), "r"(a[3]), "r"(b0), "r"(b1));
}

// hi/lo bf16 split of a float pair, packed (elem0 in low half). Bit-identical to
// the scalar version but uses packed cvt (fewer instructions).
static __device__ __forceinline__ void split2(float a0, float a1, uint32_t& hi, uint32_t& lo) {
    asm("cvt.rn.bf16x2.f32 %0, %1, %2;" : "=r"(hi) : "f"(a1), "f"(a0));
    float f0 = __uint_as_float(hi << 16);
    float f1 = __uint_as_float(hi & 0xffff0000u);
    float l0 = a0 - f0, l1 = a1 - f1;
    asm("cvt.rn.bf16x2.f32 %0, %1, %2;" : "=r"(lo) : "f"(l1), "f"(l0));
}

// weight scratch
// W1^T u32[n=256][kp=256] (kp = k/2 pairs, linear order)
__device__ __align__(16) uint32_t g_w1t_hi[2][256 * 256];
__device__ __align__(16) uint32_t g_w1t_lo[2][256 * 256];
// W2^T fragment-ordered: [n=64][kp2=128], kp2 = s*8+2t+e <-> kp = s*8+t+4e
__device__ __align__(16) uint32_t g_w2f_hi[2][64 * 128];
__device__ __align__(16) uint32_t g_w2f_lo[2][64 * 128];
// T^T * 1/8 fragment-ordered: [n=96][kp2=32], kp2 = s*8+2t+e <-> kp = s*8+t+4e
__device__ __align__(16) uint32_t g_ttf_hi[96 * 32];
__device__ __align__(16) uint32_t g_ttf_lo[96 * 32];

__global__ void prep_kernel(const float* __restrict__ Wp1, const float* __restrict__ Wv1,
                            const float* __restrict__ Wp2, const float* __restrict__ Wv2,
                            const float* __restrict__ Tm) {
    int idx = blockIdx.x * blockDim.x + threadIdx.x;
    if (idx < 65536) {
        int n = idx >> 8, kp = idx & 255;
#pragma unroll
        for (int p = 0; p < 2; ++p) {
            const float* W1 = p ? Wv1 : Wp1;
            float a0 = W1[(2 * kp) * 256 + n];
            float a1 = W1[(2 * kp + 1) * 256 + n];
            uint32_t hi, lo;
            split2(a0, a1, hi, lo);
            g_w1t_hi[p][n * 256 + kp] = hi;
            g_w1t_lo[p][n * 256 + kp] = lo;
        }
    } else if (idx < 65536 + 8192) {
        int j = idx - 65536;
        int n = j >> 7, kp2 = j & 127;
        int s = kp2 >> 3, r3 = kp2 & 7, t2 = r3 >> 1, e = r3 & 1;
        int kp = s * 8 + t2 + 4 * e;
#pragma unroll
        for (int p = 0; p < 2; ++p) {
            const float* W2 = p ? Wv2 : Wp2;
            float a0 = W2[(2 * kp) * 64 + n];
            float a1 = W2[(2 * kp + 1) * 64 + n];
            uint32_t hi, lo;
            split2(a0, a1, hi, lo);
            g_w2f_hi[p][n * 128 + kp2] = hi;
            g_w2f_lo[p][n * 128 + kp2] = lo;
        }
    } else if (idx < 65536 + 8192 + 3072) {
        int j = idx - 65536 - 8192;
        int nrow = j >> 5, kp2 = j & 31;
        int s = kp2 >> 3, r3 = kp2 & 7, t2 = r3 >> 1, e = r3 & 1;
        int kp = s * 8 + t2 + 4 * e;
        float a0 = 0.f, a1 = 0.f;
        if (nrow < 95) {
            a0 = Tm[nrow * 64 + 2 * kp] * 0.125f;
            a1 = Tm[nrow * 64 + 2 * kp + 1] * 0.125f;
        }
        uint32_t hi, lo;
        split2(a0, a1, hi, lo);
        g_ttf_hi[nrow * 32 + kp2] = hi;
        g_ttf_lo[nrow * 32 + kp2] = lo;
    }
}

__global__ __launch_bounds__(NT, 1)
void clifford_mma_kernel(
    const float* __restrict__ h_perp, const float* __restrict__ h_vuln,
    const float* __restrict__ bp1, const float* __restrict__ lgp,
    const float* __restrict__ lbp, const float* __restrict__ bp2,
    const float* __restrict__ bv1, const float* __restrict__ lgv,
    const float* __restrict__ lbv, const float* __restrict__ bv2,
    const float* __restrict__ gw,
    float* __restrict__ out)
{
    extern __shared__ char smem[];
    const uint32_t sb = smem_u32(smem);
    const int tid = threadIdx.x;
    const int lane = tid & 31;
    const int wid = tid >> 5;
    const int wm = wid & 3;       // GEMM1 m-block: rows wm*32..+32
    const int wn = wid >> 2;      // GEMM1 n-block: cols wn*64..+64
    const int wm2 = wid & 7;      // GEMM2/T-GEMM m-block: rows wm2*16..+16
    const int wn2 = wid >> 3;     // GEMM2 n-block: cols wn2*32 / T: wn2*48
    const int g = lane >> 2, t = lane & 3;
    const int g8 = lane & 7, m4 = lane >> 3;
    const int r0 = blockIdx.x * TB;

    float* mbuf  = (float*)(smem + OFF_MB);
    float* stats = (float*)(smem + OFF_ST);

    for (int p = 0; p < 2; ++p) {
        const float* hsrc = p ? h_vuln : h_perp;
        const uint32_t* w1h = g_w1t_hi[p];
        const uint32_t* w1l = g_w1t_lo[p];
        const uint32_t* w2h = g_w2f_hi[p];
        const uint32_t* w2l = g_w2f_lo[p];
        const float* b1 = p ? bv1 : bp1;
        const float* lg = p ? lgv : lgp;
        const float* lb = p ? lbv : lbp;
        const float* b2 = p ? bv2 : bp2;

        // ===== GEMM1: acc[128,256] = h @ W1, warp tile 32x64 =====
        float acc[2][8][4];
#pragma unroll
        for (int mi = 0; mi < 2; ++mi)
#pragma unroll
            for (int j = 0; j < 8; ++j)
#pragma unroll
                for (int q = 0; q < 4; ++q) acc[mi][j][q] = 0.f;

        for (int kk = 0; kk < 512; kk += 64) {
            __syncthreads();
            // A staging: 128x64 fp32 -> bf16 hi/lo, row stride 144B
#pragma unroll
            for (int z = 0; z < 4; ++z) {
                int i = tid + z * NT;
                int row = i >> 4, gq = i & 15;
                float4 v = *(const float4*)(hsrc + (size_t)(r0 + row) * 512 + kk + gq * 4);
                uint32_t h0, l0, h1, l1;
                split2(v.x, v.y, h0, l0);
                split2(v.z, v.w, h1, l1);
                char* base = smem + OFF_A1 + row * 144 + gq * 8;
                *(uint2*)(base)        = make_uint2(h0, h1);
                *(uint2*)(base + A1LO) = make_uint2(l0, l1);
            }
            // B staging: copy w1t chunk 256x(32 u32), row stride 144B
#pragma unroll
            for (int z = 0; z < 4; ++z) {
                int i = tid + z * NT;
                int row = i >> 3, q = i & 7;
                uint4 vh = *(const uint4*)(w1h + row * 256 + (kk >> 1) + q * 4);
                uint4 vl = *(const uint4*)(w1l + row * 256 + (kk >> 1) + q * 4);
                char* base = smem + OFF_B1 + row * 144 + q * 16;
                *(uint4*)(base)        = vh;
                *(uint4*)(base + B1LO) = vl;
            }
            __syncthreads();

            for (int s = 0; s < 4; ++s) {
                int kb = s * 16;
                uint32_t ah[2][4], al[2][4];
#pragma unroll
                for (int mi = 0; mi < 2; ++mi) {
                    int arow = wm * 32 + mi * 16 + g8 + ((m4 & 1) << 3);
                    int acol = kb + ((m4 & 2) << 2);
                    uint32_t ao = sb + OFF_A1 + arow * 144 + acol * 2;
                    ldsm4(ah[mi], ao);
                    ldsm4(al[mi], ao + A1LO);
                }
#pragma unroll
                for (int jh = 0; jh < 2; ++jh) {
                    uint32_t bh[2][4], bl[2][4];
#pragma unroll
                    for (int j2 = 0; j2 < 2; ++j2) {
                        int jp = jh * 2 + j2;
                        int brow = wn * 64 + jp * 16 + g8 + ((m4 & 2) << 2);
                        int bcol = kb + ((m4 & 1) << 3);
                        uint32_t bo = sb + OFF_B1 + brow * 144 + bcol * 2;
                        ldsm4(bh[j2], bo);
                        ldsm4(bl[j2], bo + B1LO);
                    }
#pragma unroll
                    for (int j2 = 0; j2 < 2; ++j2)
#pragma unroll
                        for (int hh = 0; hh < 2; ++hh)
#pragma unroll
                            for (int mi = 0; mi < 2; ++mi)
                                mma16816(acc[mi][(jh * 2 + j2) * 2 + hh], ah[mi],
                                         bh[j2][2 * hh], bh[j2][2 * hh + 1]);
#pragma unroll
                    for (int j2 = 0; j2 < 2; ++j2)
#pragma unroll
                        for (int hh = 0; hh < 2; ++hh)
#pragma unroll
                            for (int mi = 0; mi < 2; ++mi)
                                mma16816(acc[mi][(jh * 2 + j2) * 2 + hh], ah[mi],
                                         bl[j2][2 * hh], bl[j2][2 * hh + 1]);
#pragma unroll
                    for (int j2 = 0; j2 < 2; ++j2)
#pragma unroll
                        for (int hh = 0; hh < 2; ++hh)
#pragma unroll
                            for (int mi = 0; mi < 2; ++mi)
                                mma16816(acc[mi][(jh * 2 + j2) * 2 + hh], al[mi],
                                         bh[j2][2 * hh], bh[j2][2 * hh + 1]);
                }
            }
        }

        // ===== LayerNorm stats =====
        float s1[2][2] = {{0.f, 0.f}, {0.f, 0.f}};
        float s2a[2][2] = {{0.f, 0.f}, {0.f, 0.f}};
#pragma unroll
        for (int j = 0; j < 8; ++j) {
            float2 b1v = *(const float2*)(b1 + wn * 64 + 8 * j + 2 * t);
#pragma unroll
            for (int mi = 0; mi < 2; ++mi) {
                float v0 = acc[mi][j][0] + b1v.x, v1 = acc[mi][j][1] + b1v.y;
                float v2 = acc[mi][j][2] + b1v.x, v3 = acc[mi][j][3] + b1v.y;
                s1[mi][0] += v0 + v1;  s2a[mi][0] += v0 * v0 + v1 * v1;
                s1[mi][1] += v2 + v3;  s2a[mi][1] += v2 * v2 + v3 * v3;
            }
        }
#pragma unroll
        for (int mi = 0; mi < 2; ++mi)
#pragma unroll
            for (int rp = 0; rp < 2; ++rp) {
                s1[mi][rp]  += __shfl_xor_sync(0xFFFFFFFFu, s1[mi][rp], 1);
                s1[mi][rp]  += __shfl_xor_sync(0xFFFFFFFFu, s1[mi][rp], 2);
                s2a[mi][rp] += __shfl_xor_sync(0xFFFFFFFFu, s2a[mi][rp], 1);
                s2a[mi][rp] += __shfl_xor_sync(0xFFFFFFFFu, s2a[mi][rp], 2);
            }
        if (t == 0) {
#pragma unroll
            for (int mi = 0; mi < 2; ++mi)
#pragma unroll
                for (int rp = 0; rp < 2; ++rp) {
                    int row = wm * 32 + mi * 16 + g + 8 * rp;
                    stats[row * 8 + wn * 2]     = s1[mi][rp];
                    stats[row * 8 + wn * 2 + 1] = s2a[mi][rp];
                }
        }
        __syncthreads();
        float mu[2][2], rs[2][2];
#pragma unroll
        for (int mi = 0; mi < 2; ++mi)
#pragma unroll
            for (int rp = 0; rp < 2; ++rp) {
                int row = wm * 32 + mi * 16 + g + 8 * rp;
                float S  = stats[row * 8] + stats[row * 8 + 2] + stats[row * 8 + 4] + stats[row * 8 + 6];
                float S2 = stats[row * 8 + 1] + stats[row * 8 + 3] + stats[row * 8 + 5] + stats[row * 8 + 7];
                float m = S * (1.f / 256.f);
                float var = S2 * (1.f / 256.f) - m * m;
                mu[mi][rp] = m;
                rs[mi][rp] = rsqrtf(var + 1e-5f);
            }
        __syncthreads();   // staging reads done before X overwrites region

        // ===== GELU + pack -> x slabs (hi/lo, SW128 swizzled 128B rows) =====
        const int xbase = OFF_X + wn * 16384;
#pragma unroll
        for (int j = 0; j < 8; ++j) {
            int cg = wn * 64 + 8 * j + 2 * t;
            float2 b1v = *(const float2*)(b1 + cg);
            float2 lgv = *(const float2*)(lg + cg);
            float2 lbv = *(const float2*)(lb + cg);
#pragma unroll
            for (int mi = 0; mi < 2; ++mi) {
                int rowt = wm * 32 + mi * 16 + g;
                {
                    float y0 = (acc[mi][j][0] + b1v.x - mu[mi][0]) * rs[mi][0] * lgv.x + lbv.x;
                    float y1 = (acc[mi][j][1] + b1v.y - mu[mi][0]) * rs[mi][0] * lgv.y + lbv.y;
                    float g0 = 0.5f * y0 * (1.f + erff(y0 * 0.70710678118654752f));
                    float g1 = 0.5f * y1 * (1.f + erff(y1 * 0.70710678118654752f));
                    uint32_t hh, ll;
                    split2(g0, g1, hh, ll);
                    uint32_t off = (uint32_t)(rowt * 128 + (8 * j + 2 * t) * 2);
                    *(uint32_t*)(smem + xbase + SW(off))       = hh;
                    *(uint32_t*)(smem + xbase + XLO + SW(off)) = ll;
                }
                {
                    float y0 = (acc[mi][j][2] + b1v.x - mu[mi][1]) * rs[mi][1] * lgv.x + lbv.x;
                    float y1 = (acc[mi][j][3] + b1v.y - mu[mi][1]) * rs[mi][1] * lgv.y + lbv.y;
                    float g0 = 0.5f * y0 * (1.f + erff(y0 * 0.70710678118654752f));
                    float g1 = 0.5f * y1 * (1.f + erff(y1 * 0.70710678118654752f));
                    uint32_t hh, ll;
                    split2(g0, g1, hh, ll);
                    uint32_t off = (uint32_t)((rowt + 8) * 128 + (8 * j + 2 * t) * 2);
                    *(uint32_t*)(smem + xbase + SW(off))       = hh;
                    *(uint32_t*)(smem + xbase + XLO + SW(off)) = ll;
                }
            }
        }
        __syncthreads();

        // ===== GEMM2: m[128,64] = x @ W2, warp tile 16x32, full K, no atomics =====
        float a2[4][4];
#pragma unroll
        for (int j = 0; j < 4; ++j)
#pragma unroll
            for (int q = 0; q < 4; ++q) a2[j][q] = 0.f;

        for (int s = 0; s < 16; ++s) {
            uint32_t ah[4], al[4];
            {
                int slab = s >> 2;
                int arow = wm2 * 16 + g8 + ((m4 & 1) << 3);
                int lcol = (s & 3) * 16 + ((m4 & 2) << 2);
                uint32_t off = SW((uint32_t)(arow * 128 + lcol * 2));
                ldsm4(ah, sb + OFF_X + slab * 16384 + off);
                ldsm4(al, sb + OFF_X + XLO + slab * 16384 + off);
            }
            uint2 bh[4], bl[4];
#pragma unroll
            for (int j2 = 0; j2 < 4; ++j2) {
                int nrow = wn2 * 32 + j2 * 8 + g;
                bh[j2] = *(const uint2*)(w2h + nrow * 128 + s * 8 + 2 * t);
                bl[j2] = *(const uint2*)(w2l + nrow * 128 + s * 8 + 2 * t);
            }
#pragma unroll
            for (int j2 = 0; j2 < 4; ++j2) mma16816(a2[j2], ah, bh[j2].x, bh[j2].y);
#pragma unroll
            for (int j2 = 0; j2 < 4; ++j2) mma16816(a2[j2], ah, bl[j2].x, bl[j2].y);
#pragma unroll
            for (int j2 = 0; j2 < 4; ++j2) mma16816(a2[j2], al, bh[j2].x, bh[j2].y);
        }
        // store with bias (each element written exactly once)
        float* mb = mbuf + p * 8320;
        {
            int rowt = wm2 * 16 + g;
#pragma unroll
            for (int j2 = 0; j2 < 4; ++j2) {
                int c0 = wn2 * 32 + j2 * 8 + 2 * t;
                float2 b2v = *(const float2*)(b2 + c0);
                mb[rowt * 65 + c0]           = a2[j2][0] + b2v.x;
                mb[rowt * 65 + c0 + 1]       = a2[j2][1] + b2v.y;
                mb[(rowt + 8) * 65 + c0]     = a2[j2][2] + b2v.x;
                mb[(rowt + 8) * 65 + c0 + 1] = a2[j2][3] + b2v.y;
            }
        }
        __syncthreads();
    }

    // ===== Cayley contraction with gw -> P slabs (bf16 hi/lo, SW128) =====
    float gwr[8];
#pragma unroll
    for (int n = 0; n < 8; ++n) gwr[n] = gw[n];
    const int MASKc[8] = {0, 1, 2, 4, 3, 5, 6, 7};
    {
        int row = tid & 127;
        int kb2 = (tid >> 7) * 2;
        const float* mp = mbuf + row * 65;
        const float* mv = mbuf + 8320 + row * 65;
#pragma unroll
        for (int kk2 = 0; kk2 < 2; ++kk2) {
            int k = kb2 + kk2;
            float mpv[8], mvv[8];
#pragma unroll
            for (int i = 0; i < 8; ++i) { mpv[i] = mp[k * 8 + i]; mvv[i] = mv[k * 8 + i]; }
            float Q[8];
#pragma unroll
            for (int m = 0; m < 8; ++m) {
                float q = 0.f;
#pragma unroll
                for (int j = 0; j < 8; ++j) {
                    int am = MASKc[m], bm = MASKc[j];
                    int sw = __popc((am >> 1) & bm) + __popc((am >> 2) & bm);
                    float sg = (sw & 1) ? -1.f : 1.f;
                    q += sg * gwr[MASKc[am ^ bm]] * mvv[j];
                }
                Q[m] = q;
            }
            float pvv[8];
#pragma unroll
            for (int j = 0; j < 8; ++j) {
                float pv = 0.f;
#pragma unroll
                for (int i = 0; i < 8; ++i) {
                    int am = MASKc[i], bm = MASKc[j];
                    int sw = __popc((am >> 1) & bm) + __popc((am >> 2) & bm);
                    float sg = (sw & 1) ? -1.f : 1.f;
                    pv += sg * mpv[i] * Q[MASKc[am ^ bm]];
                }
                pvv[j] = pv;
            }
#pragma unroll
            for (int j = 0; j < 8; j += 2) {
                uint32_t hh, ll;
                split2(pvv[j], pvv[j + 1], hh, ll);
                uint32_t off = SW((uint32_t)(row * 128 + (k * 8 + j) * 2));
                *(uint32_t*)(smem + OFF_X + off)         = hh;
                *(uint32_t*)(smem + OFF_X + 16384 + off) = ll;
            }
        }
    }
    __syncthreads();

    // ===== T-GEMM: out[128,95] = P[128,64] @ Tt[64,96], tensor cores =====
    {
        float a3[6][4];
#pragma unroll
        for (int j = 0; j < 6; ++j)
#pragma unroll
            for (int q = 0; q < 4; ++q) a3[j][q] = 0.f;

#pragma unroll
        for (int s = 0; s < 4; ++s) {
            uint32_t ph[4], pl[4];
            {
                int arow = wm2 * 16 + g8 + ((m4 & 1) << 3);
                int lcol = s * 16 + ((m4 & 2) << 2);
                uint32_t off = SW((uint32_t)(arow * 128 + lcol * 2));
                ldsm4(ph, sb + OFF_X + off);
                ldsm4(pl, sb + OFF_X + 16384 + off);
            }
            uint2 bh[6], bl[6];
#pragma unroll
            for (int j2 = 0; j2 < 6; ++j2) {
                int nrow = wn2 * 48 + j2 * 8 + g;
                bh[j2] = *(const uint2*)(g_ttf_hi + nrow * 32 + s * 8 + 2 * t);
                bl[j2] = *(const uint2*)(g_ttf_lo + nrow * 32 + s * 8 + 2 * t);
            }
#pragma unroll
            for (int j2 = 0; j2 < 6; ++j2) mma16816(a3[j2], ph, bh[j2].x, bh[j2].y);
#pragma unroll
            for (int j2 = 0; j2 < 6; ++j2) mma16816(a3[j2], ph, bl[j2].x, bl[j2].y);
#pragma unroll
            for (int j2 = 0; j2 < 6; ++j2) mma16816(a3[j2], pl, bh[j2].x, bh[j2].y);
        }
        int rowt = r0 + wm2 * 16 + g;
#pragma unroll
        for (int j2 = 0; j2 < 6; ++j2) {
            int col = wn2 * 48 + j2 * 8 + 2 * t;
            if (col < 95) {
                out[(size_t)rowt * 95 + col]       = a3[j2][0];
                out[(size_t)(rowt + 8) * 95 + col] = a3[j2][2];
            }
            if (col + 1 < 95) {
                out[(size_t)rowt * 95 + col + 1]       = a3[j2][1];
                out[(size_t)(rowt + 8) * 95 + col + 1] = a3[j2][3];
            }
        }
    }
}

extern "C" void kernel_launch(void* const* d_in, const int* in_sizes, int n_in,
                              void* d_out, int out_size) {
    const float* h_perp = (const float*)d_in[0];
    const float* h_vuln = (const float*)d_in[1];
    const float* Wp1 = (const float*)d_in[2];
    const float* bp1 = (const float*)d_in[3];
    const float* lgp = (const float*)d_in[4];
    const float* lbp = (const float*)d_in[5];
    const float* Wp2 = (const float*)d_in[6];
    const float* bp2 = (const float*)d_in[7];
    const float* Wv1 = (const float*)d_in[8];
    const float* bv1 = (const float*)d_in[9];
    const float* lgv = (const float*)d_in[10];
    const float* lbv = (const float*)d_in[11];
    const float* Wv2 = (const float*)d_in[12];
    const float* bv2 = (const float*)d_in[13];
    const float* Tm  = (const float*)d_in[14];
    const float* gw  = (const float*)d_in[15];
    float* out = (float*)d_out;

    int B = in_sizes[0] / 512;   // 16384
    int grid = B / TB;           // 128

    prep_kernel<<<(65536 + 8192 + 3072 + 255) / 256, 256>>>(Wp1, Wv1, Wp2, Wv2, Tm);

    cudaFuncSetAttribute(clifford_mma_kernel,
                         cudaFuncAttributeMaxDynamicSharedMemorySize, SMEM_BYTES);
    clifford_mma_kernel<<<grid, NT, SMEM_BYTES>>>(
        h_perp, h_vuln, bp1, lgp, lbp, bp2, bv1, lgv, lbv, bv2, gw, out);
}

// round 11
// speedup vs baseline: 1.8133x; 1.3059x over previous
#include <cuda_runtime.h>
#include <cuda_fp16.h>
#include <cstdint>
#include <math.h>

// ----------------------------------------------------------------------------
// B=16384, D=512, H=256, R=95, KJ=64. TB=128 rows/CTA, 512 threads (16 warps),
// 1 CTA/SM. mma.sync m16n8k16 fp16.
// R11: packed-K fp16 scheme: A split exactly into fp16 hi/lo (adjacent k16
// slices), B single fp16 reused for both products: a*b = ah*bh + al*bh.
// 2 MMAs per k16 (was 3), half the B traffic. GEMM2/T-GEMM prefetch-pipelined.
// ----------------------------------------------------------------------------

#define TB 128
#define NT 512

// smem byte offsets
#define OFF_A1   0        // GEMM1 A staging [128][272] (hi/lo interleaved k16 slices)
#define OFF_B1   34816    // GEMM1 B staging [256][144] single fp16, ends 71680
#define OFF_X    0        // x slabs: [4 slab][128][272], ends 139264 (overlays staging)
#define OFF_MB   139264   // mbuf [2][128][65] f32 = 66560, ends 205824
#define OFF_ST   205824   // stats [128][8] f32 = 4096
#define SMEM_BYTES 209920
// P slab (post-GEMM2): [128][272] @ OFF_X

static __device__ __forceinline__ uint32_t smem_u32(const void* p) {
    uint32_t a;
    asm("{ .reg .u64 t; cvta.to.shared.u64 t, %1; cvt.u32.u64 %0, t; }" : "=r"(a) : "l"(p));
    return a;
}

static __device__ __forceinline__ void ldsm4(uint32_t* r, uint32_t addr) {
    asm volatile("ldmatrix.sync.aligned.m8n8.x4.shared.b16 {%0,%1,%2,%3}, [%4];"
                 : "=r"(r[0]), "=r"(r[1]), "=r"(r[2]), "=r"(r[3]) : "r"(addr));
}

static __device__ __forceinline__ void mma16816(float* c, const uint32_t* a,
                                                uint32_t b0, uint32_t b1) {
    asm volatile(
        "mma.sync.aligned.m16n8k16.row.col.f32.f16.f16.f32 "
        "{%0,%1,%2,%3}, {%4,%5,%6,%7}, {%8,%9}, {%0,%1,%2,%3};"
        : "+f"(c[0]), "+f"(c[1]), "+f"(c[2]), "+f"(c[3])
        : "r"(a[0]), "r"(a[1]), "r"(a[2]), "r"(a[3]), "r"(b0), "r"(b1));
}

static __device__ __forceinline__ void cp16(uint32_t dst, const void* src) {
    asm volatile("cp.async.cg.shared.global [%0], [%1], 16;" :: "r"(dst), "l"(src));
}

// single fp16x2 round (elem0 in low half)
static __device__ __forceinline__ uint32_t pack_h2(float a0, float a1) {
    uint32_t r;
    asm("cvt.rn.f16x2.f32 %0, %1, %2;" : "=r"(r) : "f"(a1), "f"(a0));
    return r;
}

// exact fp16 hi/lo split of a float pair, packed (elem0 in low half)
static __device__ __forceinline__ void split2h(float a0, float a1, uint32_t& hi, uint32_t& lo) {
    asm("cvt.rn.f16x2.f32 %0, %1, %2;" : "=r"(hi) : "f"(a1), "f"(a0));
    __half2 h = *reinterpret_cast<__half2*>(&hi);
    float f0 = __half2float(__low2half(h));
    float f1 = __half2float(__high2half(h));
    asm("cvt.rn.f16x2.f32 %0, %1, %2;" : "=r"(lo) : "f"(a1 - f1), "f"(a0 - f0));
}

// weight scratch (all single fp16 packed pairs)
// W1^T u32[n=256][kp=256]
__device__ __align__(16) uint32_t g_w1t[2][256 * 256];
// W2^T fragment-ordered: [n=64][kp2=128], kp2 = s*8+2t+e <-> kp = s*8+t+4e
__device__ __align__(16) uint32_t g_w2f[2][64 * 128];
// T^T * 1/8 fragment-ordered: [n=96][kp2=32]
__device__ __align__(16) uint32_t g_ttf[96 * 32];

__global__ void prep_kernel(const float* __restrict__ Wp1, const float* __restrict__ Wv1,
                            const float* __restrict__ Wp2, const float* __restrict__ Wv2,
                            const float* __restrict__ Tm) {
    int idx = blockIdx.x * blockDim.x + threadIdx.x;
    if (idx < 65536) {
        int n = idx >> 8, kp = idx & 255;
#pragma unroll
        for (int p = 0; p < 2; ++p) {
            const float* W1 = p ? Wv1 : Wp1;
            g_w1t[p][n * 256 + kp] =
                pack_h2(W1[(2 * kp) * 256 + n], W1[(2 * kp + 1) * 256 + n]);
        }
    } else if (idx < 65536 + 8192) {
        int j = idx - 65536;
        int n = j >> 7, kp2 = j & 127;
        int s = kp2 >> 3, r3 = kp2 & 7, t2 = r3 >> 1, e = r3 & 1;
        int kp = s * 8 + t2 + 4 * e;
#pragma unroll
        for (int p = 0; p < 2; ++p) {
            const float* W2 = p ? Wv2 : Wp2;
            g_w2f[p][n * 128 + kp2] =
                pack_h2(W2[(2 * kp) * 64 + n], W2[(2 * kp + 1) * 64 + n]);
        }
    } else if (idx < 65536 + 8192 + 3072) {
        int j = idx - 65536 - 8192;
        int nrow = j >> 5, kp2 = j & 31;
        int s = kp2 >> 3, r3 = kp2 & 7, t2 = r3 >> 1, e = r3 & 1;
        int kp = s * 8 + t2 + 4 * e;
        float a0 = 0.f, a1 = 0.f;
        if (nrow < 95) {
            a0 = Tm[nrow * 64 + 2 * kp] * 0.125f;
            a1 = Tm[nrow * 64 + 2 * kp + 1] * 0.125f;
        }
        g_ttf[nrow * 32 + kp2] = pack_h2(a0, a1);
    }
}

__global__ __launch_bounds__(NT, 1)
void clifford_mma_kernel(
    const float* __restrict__ h_perp, const float* __restrict__ h_vuln,
    const float* __restrict__ bp1, const float* __restrict__ lgp,
    const float* __restrict__ lbp, const float* __restrict__ bp2,
    const float* __restrict__ bv1, const float* __restrict__ lgv,
    const float* __restrict__ lbv, const float* __restrict__ bv2,
    const float* __restrict__ gw,
    float* __restrict__ out)
{
    extern __shared__ char smem[];
    const uint32_t sb = smem_u32(smem);
    const int tid = threadIdx.x;
    const int lane = tid & 31;
    const int wid = tid >> 5;
    const int wm = wid & 3;       // GEMM1 m-block: rows wm*32..+32
    const int wn = wid >> 2;      // GEMM1 n-block: cols wn*64..+64
    const int wm2 = wid & 7;      // GEMM2/T-GEMM m-block: rows wm2*16..+16
    const int wn2 = wid >> 3;     // GEMM2 n-block: cols wn2*32 / T: wn2*48
    const int g = lane >> 2, t = lane & 3;
    const int g8 = lane & 7, m4 = lane >> 3;
    const int r0 = blockIdx.x * TB;

    float* mbuf  = (float*)(smem + OFF_MB);
    float* stats = (float*)(smem + OFF_ST);

    // common fragment addressing pieces
    const int arow1 = g8 + ((m4 & 1) << 3);          // + wm*32 + mi*16
    const uint32_t acolb = (uint32_t)((m4 & 2) << 3); // hi-slice col byte offset

    for (int p = 0; p < 2; ++p) {
        const float* hsrc = p ? h_vuln : h_perp;
        const uint32_t* w1t = g_w1t[p];
        const uint32_t* w2f = g_w2f[p];
        const float* b1 = p ? bv1 : bp1;
        const float* lg = p ? lgv : lgp;
        const float* lb = p ? lbv : lbp;
        const float* b2 = p ? bv2 : bp2;

        // ===== GEMM1: acc[128,256] = h @ W1, warp tile 32x64 =====
        float acc[2][8][4];
#pragma unroll
        for (int mi = 0; mi < 2; ++mi)
#pragma unroll
            for (int j = 0; j < 8; ++j)
#pragma unroll
                for (int q = 0; q < 4; ++q) acc[mi][j][q] = 0.f;

        for (int kk = 0; kk < 512; kk += 64) {
            __syncthreads();
            // B staging via cp.async: 256 rows x 32 u32 (single fp16), stride 144
#pragma unroll
            for (int z = 0; z < 4; ++z) {
                int i = tid + z * NT;
                int row = i >> 3, q = i & 7;
                cp16(sb + OFF_B1 + (uint32_t)(row * 144 + q * 16),
                     w1t + row * 256 + (kk >> 1) + q * 4);
            }
            asm volatile("cp.async.commit_group;");
            // A staging: 128x64 fp32 -> fp16 hi/lo interleaved slices, stride 272
#pragma unroll
            for (int z = 0; z < 4; ++z) {
                int i = tid + z * NT;
                int row = i >> 4, gq = i & 15;
                float4 v = *(const float4*)(hsrc + (size_t)(r0 + row) * 512 + kk + gq * 4);
                uint32_t h0, l0, h1, l1;
                split2h(v.x, v.y, h0, l0);
                split2h(v.z, v.w, h1, l1);
                int s_loc = gq >> 2, w = gq & 3;
                char* base = smem + OFF_A1 + row * 272 + s_loc * 64 + w * 8;
                *(uint2*)(base)      = make_uint2(h0, h1);
                *(uint2*)(base + 32) = make_uint2(l0, l1);
            }
            asm volatile("cp.async.wait_group 0;");
            __syncthreads();

            for (int s = 0; s < 4; ++s) {
                uint32_t ah[2][4], al[2][4];
#pragma unroll
                for (int mi = 0; mi < 2; ++mi) {
                    uint32_t ao = sb + OFF_A1 + (uint32_t)((wm * 32 + mi * 16 + arow1) * 272
                                 + s * 64) + acolb;
                    ldsm4(ah[mi], ao);
                    ldsm4(al[mi], ao + 32);
                }
                uint32_t bfr[4][4];
#pragma unroll
                for (int jp = 0; jp < 4; ++jp) {
                    int brow = wn * 64 + jp * 16 + g8 + ((m4 & 2) << 2);
                    uint32_t bo = sb + OFF_B1 + (uint32_t)(brow * 144 + s * 32)
                                 + ((uint32_t)(m4 & 1) << 4);
                    ldsm4(bfr[jp], bo);
                }
                // pass hi: ah * b
#pragma unroll
                for (int jp = 0; jp < 4; ++jp)
#pragma unroll
                    for (int hh = 0; hh < 2; ++hh)
#pragma unroll
                        for (int mi = 0; mi < 2; ++mi)
                            mma16816(acc[mi][jp * 2 + hh], ah[mi],
                                     bfr[jp][2 * hh], bfr[jp][2 * hh + 1]);
                // pass lo: al * b (same B fragments)
#pragma unroll
                for (int jp = 0; jp < 4; ++jp)
#pragma unroll
                    for (int hh = 0; hh < 2; ++hh)
#pragma unroll
                        for (int mi = 0; mi < 2; ++mi)
                            mma16816(acc[mi][jp * 2 + hh], al[mi],
                                     bfr[jp][2 * hh], bfr[jp][2 * hh + 1]);
            }
        }

        // ===== LayerNorm stats =====
        float s1[2][2] = {{0.f, 0.f}, {0.f, 0.f}};
        float s2a[2][2] = {{0.f, 0.f}, {0.f, 0.f}};
#pragma unroll
        for (int j = 0; j < 8; ++j) {
            float2 b1v = *(const float2*)(b1 + wn * 64 + 8 * j + 2 * t);
#pragma unroll
            for (int mi = 0; mi < 2; ++mi) {
                float v0 = acc[mi][j][0] + b1v.x, v1 = acc[mi][j][1] + b1v.y;
                float v2 = acc[mi][j][2] + b1v.x, v3 = acc[mi][j][3] + b1v.y;
                s1[mi][0] += v0 + v1;  s2a[mi][0] += v0 * v0 + v1 * v1;
                s1[mi][1] += v2 + v3;  s2a[mi][1] += v2 * v2 + v3 * v3;
            }
        }
#pragma unroll
        for (int mi = 0; mi < 2; ++mi)
#pragma unroll
            for (int rp = 0; rp < 2; ++rp) {
                s1[mi][rp]  += __shfl_xor_sync(0xFFFFFFFFu, s1[mi][rp], 1);
                s1[mi][rp]  += __shfl_xor_sync(0xFFFFFFFFu, s1[mi][rp], 2);
                s2a[mi][rp] += __shfl_xor_sync(0xFFFFFFFFu, s2a[mi][rp], 1);
                s2a[mi][rp] += __shfl_xor_sync(0xFFFFFFFFu, s2a[mi][rp], 2);
            }
        if (t == 0) {
#pragma unroll
            for (int mi = 0; mi < 2; ++mi)
#pragma unroll
                for (int rp = 0; rp < 2; ++rp) {
                    int row = wm * 32 + mi * 16 + g + 8 * rp;
                    stats[row * 8 + wn * 2]     = s1[mi][rp];
                    stats[row * 8 + wn * 2 + 1] = s2a[mi][rp];
                }
        }
        __syncthreads();
        float mu[2][2], rs[2][2];
#pragma unroll
        for (int mi = 0; mi < 2; ++mi)
#pragma unroll
            for (int rp = 0; rp < 2; ++rp) {
                int row = wm * 32 + mi * 16 + g + 8 * rp;
                float S  = stats[row * 8] + stats[row * 8 + 2] + stats[row * 8 + 4] + stats[row * 8 + 6];
                float S2 = stats[row * 8 + 1] + stats[row * 8 + 3] + stats[row * 8 + 5] + stats[row * 8 + 7];
                float m = S * (1.f / 256.f);
                float var = S2 * (1.f / 256.f) - m * m;
                mu[mi][rp] = m;
                rs[mi][rp] = rsqrtf(var + 1e-5f);
            }
        __syncthreads();   // staging reads done before X overwrites region

        // ===== GELU + pack -> x slabs (fp16 hi/lo slices, stride 272) =====
        const int xbase = OFF_X + wn * 34816;
#pragma unroll
        for (int j = 0; j < 8; ++j) {
            int cl = 8 * j + 2 * t;          // local col within slab (0..63)
            int cg = wn * 64 + cl;
            float2 b1v = *(const float2*)(b1 + cg);
            float2 lgv = *(const float2*)(lg + cg);
            float2 lbv = *(const float2*)(lb + cg);
            int s2 = cl >> 4, wofs = (cl & 15) * 2;
#pragma unroll
            for (int mi = 0; mi < 2; ++mi) {
                int rowt = wm * 32 + mi * 16 + g;
                {
                    float y0 = (acc[mi][j][0] + b1v.x - mu[mi][0]) * rs[mi][0] * lgv.x + lbv.x;
                    float y1 = (acc[mi][j][1] + b1v.y - mu[mi][0]) * rs[mi][0] * lgv.y + lbv.y;
                    float g0 = 0.5f * y0 * (1.f + erff(y0 * 0.70710678118654752f));
                    float g1 = 0.5f * y1 * (1.f + erff(y1 * 0.70710678118654752f));
                    uint32_t hh, ll;
                    split2h(g0, g1, hh, ll);
                    char* base = smem + xbase + rowt * 272 + s2 * 64 + wofs;
                    *(uint32_t*)(base)      = hh;
                    *(uint32_t*)(base + 32) = ll;
                }
                {
                    float y0 = (acc[mi][j][2] + b1v.x - mu[mi][1]) * rs[mi][1] * lgv.x + lbv.x;
                    float y1 = (acc[mi][j][3] + b1v.y - mu[mi][1]) * rs[mi][1] * lgv.y + lbv.y;
                    float g0 = 0.5f * y0 * (1.f + erff(y0 * 0.70710678118654752f));
                    float g1 = 0.5f * y1 * (1.f + erff(y1 * 0.70710678118654752f));
                    uint32_t hh, ll;
                    split2h(g0, g1, hh, ll);
                    char* base = smem + xbase + (rowt + 8) * 272 + s2 * 64 + wofs;
                    *(uint32_t*)(base)      = hh;
                    *(uint32_t*)(base + 32) = ll;
                }
            }
        }
        __syncthreads();

        // ===== GEMM2: m[128,64] = x @ W2, warp tile 16x32, prefetch-pipelined =====
        float a2[4][4];
#pragma unroll
        for (int j = 0; j < 4; ++j)
#pragma unroll
            for (int q = 0; q < 4; ++q) a2[j][q] = 0.f;

        {
            const int arow2 = wm2 * 16 + arow1;
            uint32_t AH[2][4], AL[2][4];
            uint2 BF[2][4];
            // load s=0
            {
                uint32_t ao = sb + OFF_X + (uint32_t)(arow2 * 272) + acolb;
                ldsm4(AH[0], ao);
                ldsm4(AL[0], ao + 32);
#pragma unroll
                for (int j2 = 0; j2 < 4; ++j2)
                    BF[0][j2] = *(const uint2*)(w2f + (wn2 * 32 + j2 * 8 + g) * 128 + 2 * t);
            }
#pragma unroll
            for (int s = 0; s < 16; ++s) {
                int cur = s & 1, nxt = cur ^ 1;
                if (s < 15) {
                    int sn = s + 1, slab = sn >> 2, sl = sn & 3;
                    uint32_t ao = sb + OFF_X + (uint32_t)(slab * 34816 + arow2 * 272
                                 + sl * 64) + acolb;
                    ldsm4(AH[nxt], ao);
                    ldsm4(AL[nxt], ao + 32);
#pragma unroll
                    for (int j2 = 0; j2 < 4; ++j2)
                        BF[nxt][j2] = *(const uint2*)(w2f + (wn2 * 32 + j2 * 8 + g) * 128
                                      + sn * 8 + 2 * t);
                }
#pragma unroll
                for (int j2 = 0; j2 < 4; ++j2)
                    mma16816(a2[j2], AH[cur], BF[cur][j2].x, BF[cur][j2].y);
#pragma unroll
                for (int j2 = 0; j2 < 4; ++j2)
                    mma16816(a2[j2], AL[cur], BF[cur][j2].x, BF[cur][j2].y);
            }
        }
        // store with bias (each element written exactly once)
        float* mb = mbuf + p * 8320;
        {
            int rowt = wm2 * 16 + g;
#pragma unroll
            for (int j2 = 0; j2 < 4; ++j2) {
                int c0 = wn2 * 32 + j2 * 8 + 2 * t;
                float2 b2v = *(const float2*)(b2 + c0);
                mb[rowt * 65 + c0]           = a2[j2][0] + b2v.x;
                mb[rowt * 65 + c0 + 1]       = a2[j2][1] + b2v.y;
                mb[(rowt + 8) * 65 + c0]     = a2[j2][2] + b2v.x;
                mb[(rowt + 8) * 65 + c0 + 1] = a2[j2][3] + b2v.y;
            }
        }
        __syncthreads();
    }

    // ===== Cayley contraction with gw -> P slab (fp16 hi/lo, stride 272) =====
    float gwr[8];
#pragma unroll
    for (int n = 0; n < 8; ++n) gwr[n] = gw[n];
    const int MASKc[8] = {0, 1, 2, 4, 3, 5, 6, 7};
    {
        int row = tid & 127;
        int kb2 = (tid >> 7) * 2;
        const float* mp = mbuf + row * 65;
        const float* mv = mbuf + 8320 + row * 65;
#pragma unroll
        for (int kk2 = 0; kk2 < 2; ++kk2) {
            int k = kb2 + kk2;
            float mpv[8], mvv[8];
#pragma unroll
            for (int i = 0; i < 8; ++i) { mpv[i] = mp[k * 8 + i]; mvv[i] = mv[k * 8 + i]; }
            float Q[8];
#pragma unroll
            for (int m = 0; m < 8; ++m) {
                float q = 0.f;
#pragma unroll
                for (int j = 0; j < 8; ++j) {
                    int am = MASKc[m], bm = MASKc[j];
                    int sw = __popc((am >> 1) & bm) + __popc((am >> 2) & bm);
                    float sg = (sw & 1) ? -1.f : 1.f;
                    q += sg * gwr[MASKc[am ^ bm]] * mvv[j];
                }
                Q[m] = q;
            }
            float pvv[8];
#pragma unroll
            for (int j = 0; j < 8; ++j) {
                float pv = 0.f;
#pragma unroll
                for (int i = 0; i < 8; ++i) {
                    int am = MASKc[i], bm = MASKc[j];
                    int sw = __popc((am >> 1) & bm) + __popc((am >> 2) & bm);
                    float sg = (sw & 1) ? -1.f : 1.f;
                    pv += sg * mpv[i] * Q[MASKc[am ^ bm]];
                }
                pvv[j] = pv;
            }
#pragma unroll
            for (int j = 0; j < 8; j += 2) {
                uint32_t hh, ll;
                split2h(pvv[j], pvv[j + 1], hh, ll);
                char* base = smem + OFF_X + row * 272 + (k >> 1) * 64 + (k & 1) * 16 + j * 2;
                *(uint32_t*)(base)      = hh;
                *(uint32_t*)(base + 32) = ll;
            }
        }
    }
    __syncthreads();

    // ===== T-GEMM: out[128,95] = P[128,64] @ Tt[64,96], prefetch-pipelined =====
    {
        float a3[6][4];
#pragma unroll
        for (int j = 0; j < 6; ++j)
#pragma unroll
            for (int q = 0; q < 4; ++q) a3[j][q] = 0.f;

        const int arow2 = wm2 * 16 + arow1;
        uint32_t PH[2][4], PL[2][4];
        uint2 TF[2][6];
        {
            uint32_t ao = sb + OFF_X + (uint32_t)(arow2 * 272) + acolb;
            ldsm4(PH[0], ao);
            ldsm4(PL[0], ao + 32);
#pragma unroll
            for (int j2 = 0; j2 < 6; ++j2)
                TF[0][j2] = *(const uint2*)(g_ttf + (wn2 * 48 + j2 * 8 + g) * 32 + 2 * t);
        }
#pragma unroll
        for (int s = 0; s < 4; ++s) {
            int cur = s & 1, nxt = cur ^ 1;
            if (s < 3) {
                int sn = s + 1;
                uint32_t ao = sb + OFF_X + (uint32_t)(arow2 * 272 + sn * 64) + acolb;
                ldsm4(PH[nxt], ao);
                ldsm4(PL[nxt], ao + 32);
#pragma unroll
                for (int j2 = 0; j2 < 6; ++j2)
                    TF[nxt][j2] = *(const uint2*)(g_ttf + (wn2 * 48 + j2 * 8 + g) * 32
                                  + sn * 8 + 2 * t);
            }
#pragma unroll
            for (int j2 = 0; j2 < 6; ++j2)
                mma16816(a3[j2], PH[cur], TF[cur][j2].x, TF[cur][j2].y);
#pragma unroll
            for (int j2 = 0; j2 < 6; ++j2)
                mma16816(a3[j2], PL[cur], TF[cur][j2].x, TF[cur][j2].y);
        }
        int rowt = r0 + wm2 * 16 + g;
#pragma unroll
        for (int j2 = 0; j2 < 6; ++j2) {
            int col = wn2 * 48 + j2 * 8 + 2 * t;
            if (col < 95) {
                out[(size_t)rowt * 95 + col]       = a3[j2][0];
                out[(size_t)(rowt + 8) * 95 + col] = a3[j2][2];
            }
            if (col + 1 < 95) {
                out[(size_t)rowt * 95 + col + 1]       = a3[j2][1];
                out[(size_t)(rowt + 8) * 95 + col + 1] = a3[j2][3];
            }
        }
    }
}

extern "C" void kernel_launch(void* const* d_in, const int* in_sizes, int n_in,
                              void* d_out, int out_size) {
    const float* h_perp = (const float*)d_in[0];
    const float* h_vuln = (const float*)d_in[1];
    const float* Wp1 = (const float*)d_in[2];
    const float* bp1 = (const float*)d_in[3];
    const float* lgp = (const float*)d_in[4];
    const float* lbp = (const float*)d_in[5];
    const float* Wp2 = (const float*)d_in[6];
    const float* bp2 = (const float*)d_in[7];
    const float* Wv1 = (const float*)d_in[8];
    const float* bv1 = (const float*)d_in[9];
    const float* lgv = (const float*)d_in[10];
    const float* lbv = (const float*)d_in[11];
    const float* Wv2 = (const float*)d_in[12];
    const float* bv2 = (const float*)d_in[13];
    const float* Tm  = (const float*)d_in[14];
    const float* gw  = (const float*)d_in[15];
    float* out = (float*)d_out;

    int B = in_sizes[0] / 512;   // 16384
    int grid = B / TB;           // 128

    prep_kernel<<<(65536 + 8192 + 3072 + 255) / 256, 256>>>(Wp1, Wv1, Wp2, Wv2, Tm);

    cudaFuncSetAttribute(clifford_mma_kernel,
                         cudaFuncAttributeMaxDynamicSharedMemorySize, SMEM_BYTES);
    clifford_mma_kernel<<<grid, NT, SMEM_BYTES>>>(
        h_perp, h_vuln, bp1, lgp, lbp, bp2, bv1, lgv, lbv, bv2, gw, out);
}

// round 13
// speedup vs baseline: 1.9417x; 1.0708x over previous
#include <cuda_runtime.h>
#include <cuda_fp16.h>
#include <cstdint>
#include <math.h>

// ----------------------------------------------------------------------------
// B=16384, D=512, H=256, R=95, KJ=64. TB=64 rows/CTA, 256 threads (8 warps,
// 2m x 4n warp grid, warp tile 32x64 identical to R11), 2 CTAs/SM, grid=256
// (single wave). mma.sync m16n8k16 fp16, packed-K scheme: A exact fp16 hi/lo,
// B single fp16: a*b = ah*b + al*b.
// ----------------------------------------------------------------------------

#define TB 64
#define NT 256

// smem byte offsets
#define OFF_A1   0        // GEMM1 A staging [64][272] (hi/lo interleaved k16 slices)
#define OFF_B1   17408    // GEMM1 B staging [256][144] single fp16, ends 54272
#define OFF_X    0        // x slabs: [4 slab][64][272] = 69632 (overlays staging)
#define OFF_MB   69632    // mbuf [2][64][65] f32 = 33280, ends 102912
#define OFF_ST   102912   // stats [64][8] f32 = 2048
#define SMEM_BYTES 104960
// P slab (post-GEMM2): [64][272] @ OFF_X

static __device__ __forceinline__ uint32_t smem_u32(const void* p) {
    uint32_t a;
    asm("{ .reg .u64 t; cvta.to.shared.u64 t, %1; cvt.u32.u64 %0, t; }" : "=r"(a) : "l"(p));
    return a;
}

static __device__ __forceinline__ void ldsm4(uint32_t* r, uint32_t addr) {
    asm volatile("ldmatrix.sync.aligned.m8n8.x4.shared.b16 {%0,%1,%2,%3}, [%4];"
                 : "=r"(r[0]), "=r"(r[1]), "=r"(r[2]), "=r"(r[3]) : "r"(addr));
}

static __device__ __forceinline__ void mma16816(float* c, const uint32_t* a,
                                                uint32_t b0, uint32_t b1) {
    asm volatile(
        "mma.sync.aligned.m16n8k16.row.col.f32.f16.f16.f32 "
        "{%0,%1,%2,%3}, {%4,%5,%6,%7}, {%8,%9}, {%0,%1,%2,%3};"
        : "+f"(c[0]), "+f"(c[1]), "+f"(c[2]), "+f"(c[3])
        : "r"(a[0]), "r"(a[1]), "r"(a[2]), "r"(a[3]), "r"(b0), "r"(b1));
}

static __device__ __forceinline__ void cp16(uint32_t dst, const void* src) {
    asm volatile("cp.async.cg.shared.global [%0], [%1], 16;" :: "r"(dst), "l"(src));
}

// single fp16x2 round (elem0 in low half)
static __device__ __forceinline__ uint32_t pack_h2(float a0, float a1) {
    uint32_t r;
    asm("cvt.rn.f16x2.f32 %0, %1, %2;" : "=r"(r) : "f"(a1), "f"(a0));
    return r;
}

// exact fp16 hi/lo split of a float pair, packed (elem0 in low half)
static __device__ __forceinline__ void split2h(float a0, float a1, uint32_t& hi, uint32_t& lo) {
    asm("cvt.rn.f16x2.f32 %0, %1, %2;" : "=r"(hi) : "f"(a1), "f"(a0));
    __half2 h = *reinterpret_cast<__half2*>(&hi);
    float f0 = __half2float(__low2half(h));
    float f1 = __half2float(__high2half(h));
    asm("cvt.rn.f16x2.f32 %0, %1, %2;" : "=r"(lo) : "f"(a1 - f1), "f"(a0 - f0));
}

// weight scratch (all single fp16 packed pairs)
__device__ __align__(16) uint32_t g_w1t[2][256 * 256];   // W1^T [n=256][kp=256]
__device__ __align__(16) uint32_t g_w2f[2][64 * 128];    // W2^T frag-ordered
__device__ __align__(16) uint32_t g_ttf[96 * 32];        // T^T/8 frag-ordered

__global__ void prep_kernel(const float* __restrict__ Wp1, const float* __restrict__ Wv1,
                            const float* __restrict__ Wp2, const float* __restrict__ Wv2,
                            const float* __restrict__ Tm) {
    int idx = blockIdx.x * blockDim.x + threadIdx.x;
    if (idx < 65536) {
        int n = idx >> 8, kp = idx & 255;
#pragma unroll
        for (int p = 0; p < 2; ++p) {
            const float* W1 = p ? Wv1 : Wp1;
            g_w1t[p][n * 256 + kp] =
                pack_h2(W1[(2 * kp) * 256 + n], W1[(2 * kp + 1) * 256 + n]);
        }
    } else if (idx < 65536 + 8192) {
        int j = idx - 65536;
        int n = j >> 7, kp2 = j & 127;
        int s = kp2 >> 3, r3 = kp2 & 7, t2 = r3 >> 1, e = r3 & 1;
        int kp = s * 8 + t2 + 4 * e;
#pragma unroll
        for (int p = 0; p < 2; ++p) {
            const float* W2 = p ? Wv2 : Wp2;
            g_w2f[p][n * 128 + kp2] =
                pack_h2(W2[(2 * kp) * 64 + n], W2[(2 * kp + 1) * 64 + n]);
        }
    } else if (idx < 65536 + 8192 + 3072) {
        int j = idx - 65536 - 8192;
        int nrow = j >> 5, kp2 = j & 31;
        int s = kp2 >> 3, r3 = kp2 & 7, t2 = r3 >> 1, e = r3 & 1;
        int kp = s * 8 + t2 + 4 * e;
        float a0 = 0.f, a1 = 0.f;
        if (nrow < 95) {
            a0 = Tm[nrow * 64 + 2 * kp] * 0.125f;
            a1 = Tm[nrow * 64 + 2 * kp + 1] * 0.125f;
        }
        g_ttf[nrow * 32 + kp2] = pack_h2(a0, a1);
    }
}

__global__ __launch_bounds__(NT, 2)
void clifford_mma_kernel(
    const float* __restrict__ h_perp, const float* __restrict__ h_vuln,
    const float* __restrict__ bp1, const float* __restrict__ lgp,
    const float* __restrict__ lbp, const float* __restrict__ bp2,
    const float* __restrict__ bv1, const float* __restrict__ lgv,
    const float* __restrict__ lbv, const float* __restrict__ bv2,
    const float* __restrict__ gw,
    float* __restrict__ out)
{
    extern __shared__ char smem[];
    const uint32_t sb = smem_u32(smem);
    const int tid = threadIdx.x;
    const int lane = tid & 31;
    const int wid = tid >> 5;     // 0..7
    const int wm = wid & 1;       // GEMM1 m-block: rows wm*32..+32
    const int wn = wid >> 1;      // GEMM1 n-block: cols wn*64..+64
    const int wm2 = wid & 3;      // GEMM2/T-GEMM m-block: rows wm2*16..+16
    const int wn2 = wid >> 2;     // GEMM2 n-block: cols wn2*32 / T: wn2*48
    const int g = lane >> 2, t = lane & 3;
    const int g8 = lane & 7, m4 = lane >> 3;
    const int r0 = blockIdx.x * TB;

    float* mbuf  = (float*)(smem + OFF_MB);
    float* stats = (float*)(smem + OFF_ST);

    // common fragment addressing pieces
    const int arow1 = g8 + ((m4 & 1) << 3);
    const uint32_t acolb = (uint32_t)((m4 & 2) << 3);

    for (int p = 0; p < 2; ++p) {
        const float* hsrc = p ? h_vuln : h_perp;
        const uint32_t* w1t = g_w1t[p];
        const uint32_t* w2f = g_w2f[p];
        const float* b1 = p ? bv1 : bp1;
        const float* lg = p ? lgv : lgp;
        const float* lb = p ? lbv : lbp;
        const float* b2 = p ? bv2 : bp2;

        // ===== GEMM1: acc[64,256] = h @ W1, warp tile 32x64 =====
        float acc[2][8][4];
#pragma unroll
        for (int mi = 0; mi < 2; ++mi)
#pragma unroll
            for (int j = 0; j < 8; ++j)
#pragma unroll
                for (int q = 0; q < 4; ++q) acc[mi][j][q] = 0.f;

        for (int kk = 0; kk < 512; kk += 64) {
            __syncthreads();
            // B staging via cp.async: 256 rows x 32 u32 (single fp16), stride 144
#pragma unroll
            for (int z = 0; z < 8; ++z) {
                int i = tid + z * NT;
                int row = i >> 3, q = i & 7;
                cp16(sb + OFF_B1 + (uint32_t)(row * 144 + q * 16),
                     w1t + row * 256 + (kk >> 1) + q * 4);
            }
            asm volatile("cp.async.commit_group;");
            // A staging: 64x64 fp32 -> fp16 hi/lo interleaved slices, stride 272
#pragma unroll
            for (int z = 0; z < 4; ++z) {
                int i = tid + z * NT;
                int row = i >> 4, gq = i & 15;
                float4 v = *(const float4*)(hsrc + (size_t)(r0 + row) * 512 + kk + gq * 4);
                uint32_t h0, l0, h1, l1;
                split2h(v.x, v.y, h0, l0);
                split2h(v.z, v.w, h1, l1);
                int s_loc = gq >> 2, w = gq & 3;
                char* base = smem + OFF_A1 + row * 272 + s_loc * 64 + w * 8;
                *(uint2*)(base)      = make_uint2(h0, h1);
                *(uint2*)(base + 32) = make_uint2(l0, l1);
            }
            asm volatile("cp.async.wait_group 0;");
            __syncthreads();

            for (int s = 0; s < 4; ++s) {
                uint32_t ah[2][4], al[2][4];
#pragma unroll
                for (int mi = 0; mi < 2; ++mi) {
                    uint32_t ao = sb + OFF_A1 + (uint32_t)((wm * 32 + mi * 16 + arow1) * 272
                                 + s * 64) + acolb;
                    ldsm4(ah[mi], ao);
                    ldsm4(al[mi], ao + 32);
                }
                uint32_t bfr[4][4];
#pragma unroll
                for (int jp = 0; jp < 4; ++jp) {
                    int brow = wn * 64 + jp * 16 + g8 + ((m4 & 2) << 2);
                    uint32_t bo = sb + OFF_B1 + (uint32_t)(brow * 144 + s * 32)
                                 + ((uint32_t)(m4 & 1) << 4);
                    ldsm4(bfr[jp], bo);
                }
#pragma unroll
                for (int jp = 0; jp < 4; ++jp)
#pragma unroll
                    for (int hh = 0; hh < 2; ++hh)
#pragma unroll
                        for (int mi = 0; mi < 2; ++mi)
                            mma16816(acc[mi][jp * 2 + hh], ah[mi],
                                     bfr[jp][2 * hh], bfr[jp][2 * hh + 1]);
#pragma unroll
                for (int jp = 0; jp < 4; ++jp)
#pragma unroll
                    for (int hh = 0; hh < 2; ++hh)
#pragma unroll
                        for (int mi = 0; mi < 2; ++mi)
                            mma16816(acc[mi][jp * 2 + hh], al[mi],
                                     bfr[jp][2 * hh], bfr[jp][2 * hh + 1]);
            }
        }

        // ===== LayerNorm stats (bias folded into acc in place) =====
        float s1[2][2] = {{0.f, 0.f}, {0.f, 0.f}};
        float s2a[2][2] = {{0.f, 0.f}, {0.f, 0.f}};
#pragma unroll
        for (int j = 0; j < 8; ++j) {
            float2 b1v = *(const float2*)(b1 + wn * 64 + 8 * j + 2 * t);
#pragma unroll
            for (int mi = 0; mi < 2; ++mi) {
                float v0 = acc[mi][j][0] + b1v.x, v1 = acc[mi][j][1] + b1v.y;
                float v2 = acc[mi][j][2] + b1v.x, v3 = acc[mi][j][3] + b1v.y;
                acc[mi][j][0] = v0; acc[mi][j][1] = v1;
                acc[mi][j][2] = v2; acc[mi][j][3] = v3;
                s1[mi][0] += v0 + v1;  s2a[mi][0] += v0 * v0 + v1 * v1;
                s1[mi][1] += v2 + v3;  s2a[mi][1] += v2 * v2 + v3 * v3;
            }
        }
#pragma unroll
        for (int mi = 0; mi < 2; ++mi)
#pragma unroll
            for (int rp = 0; rp < 2; ++rp) {
                s1[mi][rp]  += __shfl_xor_sync(0xFFFFFFFFu, s1[mi][rp], 1);
                s1[mi][rp]  += __shfl_xor_sync(0xFFFFFFFFu, s1[mi][rp], 2);
                s2a[mi][rp] += __shfl_xor_sync(0xFFFFFFFFu, s2a[mi][rp], 1);
                s2a[mi][rp] += __shfl_xor_sync(0xFFFFFFFFu, s2a[mi][rp], 2);
            }
        if (t == 0) {
#pragma unroll
            for (int mi = 0; mi < 2; ++mi)
#pragma unroll
                for (int rp = 0; rp < 2; ++rp) {
                    int row = wm * 32 + mi * 16 + g + 8 * rp;
                    stats[row * 8 + wn * 2]     = s1[mi][rp];
                    stats[row * 8 + wn * 2 + 1] = s2a[mi][rp];
                }
        }
        __syncthreads();
        float mu[2][2], rs[2][2];
#pragma unroll
        for (int mi = 0; mi < 2; ++mi)
#pragma unroll
            for (int rp = 0; rp < 2; ++rp) {
                int row = wm * 32 + mi * 16 + g + 8 * rp;
                float S  = stats[row * 8] + stats[row * 8 + 2] + stats[row * 8 + 4] + stats[row * 8 + 6];
                float S2 = stats[row * 8 + 1] + stats[row * 8 + 3] + stats[row * 8 + 5] + stats[row * 8 + 7];
                float m = S * (1.f / 256.f);
                float var = S2 * (1.f / 256.f) - m * m;
                mu[mi][rp] = m;
                rs[mi][rp] = rsqrtf(var + 1e-5f);
            }
        __syncthreads();   // staging reads done before X overwrites region

        // ===== GELU + pack -> x slabs (fp16 hi/lo slices, stride 272) =====
        const int xbase = OFF_X + wn * 17408;
#pragma unroll
        for (int j = 0; j < 8; ++j) {
            int cl = 8 * j + 2 * t;
            int cg = wn * 64 + cl;
            float2 lgv = *(const float2*)(lg + cg);
            float2 lbv = *(const float2*)(lb + cg);
            int s2 = cl >> 4, wofs = (cl & 15) * 2;
#pragma unroll
            for (int mi = 0; mi < 2; ++mi) {
                int rowt = wm * 32 + mi * 16 + g;
                {
                    float y0 = (acc[mi][j][0] - mu[mi][0]) * rs[mi][0] * lgv.x + lbv.x;
                    float y1 = (acc[mi][j][1] - mu[mi][0]) * rs[mi][0] * lgv.y + lbv.y;
                    float g0 = 0.5f * y0 * (1.f + erff(y0 * 0.70710678118654752f));
                    float g1 = 0.5f * y1 * (1.f + erff(y1 * 0.70710678118654752f));
                    uint32_t hh, ll;
                    split2h(g0, g1, hh, ll);
                    char* base = smem + xbase + rowt * 272 + s2 * 64 + wofs;
                    *(uint32_t*)(base)      = hh;
                    *(uint32_t*)(base + 32) = ll;
                }
                {
                    float y0 = (acc[mi][j][2] - mu[mi][1]) * rs[mi][1] * lgv.x + lbv.x;
                    float y1 = (acc[mi][j][3] - mu[mi][1]) * rs[mi][1] * lgv.y + lbv.y;
                    float g0 = 0.5f * y0 * (1.f + erff(y0 * 0.70710678118654752f));
                    float g1 = 0.5f * y1 * (1.f + erff(y1 * 0.70710678118654752f));
                    uint32_t hh, ll;
                    split2h(g0, g1, hh, ll);
                    char* base = smem + xbase + (rowt + 8) * 272 + s2 * 64 + wofs;
                    *(uint32_t*)(base)      = hh;
                    *(uint32_t*)(base + 32) = ll;
                }
            }
        }
        __syncthreads();

        // ===== GEMM2: m[64,64] = x @ W2, warp tile 16x32, prefetch-pipelined =====
        float a2[4][4];
#pragma unroll
        for (int j = 0; j < 4; ++j)
#pragma unroll
            for (int q = 0; q < 4; ++q) a2[j][q] = 0.f;

        {
            const int arow2 = wm2 * 16 + arow1;
            uint32_t AH[2][4], AL[2][4];
            uint2 BF[2][4];
            {
                uint32_t ao = sb + OFF_X + (uint32_t)(arow2 * 272) + acolb;
                ldsm4(AH[0], ao);
                ldsm4(AL[0], ao + 32);
#pragma unroll
                for (int j2 = 0; j2 < 4; ++j2)
                    BF[0][j2] = *(const uint2*)(w2f + (wn2 * 32 + j2 * 8 + g) * 128 + 2 * t);
            }
#pragma unroll
            for (int s = 0; s < 16; ++s) {
                int cur = s & 1, nxt = cur ^ 1;
                if (s < 15) {
                    int sn = s + 1, slab = sn >> 2, sl = sn & 3;
                    uint32_t ao = sb + OFF_X + (uint32_t)(slab * 17408 + arow2 * 272
                                 + sl * 64) + acolb;
                    ldsm4(AH[nxt], ao);
                    ldsm4(AL[nxt], ao + 32);
#pragma unroll
                    for (int j2 = 0; j2 < 4; ++j2)
                        BF[nxt][j2] = *(const uint2*)(w2f + (wn2 * 32 + j2 * 8 + g) * 128
                                      + sn * 8 + 2 * t);
                }
#pragma unroll
                for (int j2 = 0; j2 < 4; ++j2)
                    mma16816(a2[j2], AH[cur], BF[cur][j2].x, BF[cur][j2].y);
#pragma unroll
                for (int j2 = 0; j2 < 4; ++j2)
                    mma16816(a2[j2], AL[cur], BF[cur][j2].x, BF[cur][j2].y);
            }
        }
        float* mb = mbuf + p * 4160;
        {
            int rowt = wm2 * 16 + g;
#pragma unroll
            for (int j2 = 0; j2 < 4; ++j2) {
                int c0 = wn2 * 32 + j2 * 8 + 2 * t;
                float2 b2v = *(const float2*)(b2 + c0);
                mb[rowt * 65 + c0]           = a2[j2][0] + b2v.x;
                mb[rowt * 65 + c0 + 1]       = a2[j2][1] + b2v.y;
                mb[(rowt + 8) * 65 + c0]     = a2[j2][2] + b2v.x;
                mb[(rowt + 8) * 65 + c0 + 1] = a2[j2][3] + b2v.y;
            }
        }
        __syncthreads();
    }

    // ===== Cayley contraction with gw -> P slab (fp16 hi/lo, stride 272) =====
    float gwr[8];
#pragma unroll
    for (int n = 0; n < 8; ++n) gwr[n] = gw[n];
    const int MASKc[8] = {0, 1, 2, 4, 3, 5, 6, 7};
    {
        int row = tid & 63;
        int kb2 = (tid >> 6) * 2;
        const float* mp = mbuf + row * 65;
        const float* mv = mbuf + 4160 + row * 65;
#pragma unroll
        for (int kk2 = 0; kk2 < 2; ++kk2) {
            int k = kb2 + kk2;
            float mpv[8], mvv[8];
#pragma unroll
            for (int i = 0; i < 8; ++i) { mpv[i] = mp[k * 8 + i]; mvv[i] = mv[k * 8 + i]; }
            float Q[8];
#pragma unroll
            for (int m = 0; m < 8; ++m) {
                float q = 0.f;
#pragma unroll
                for (int j = 0; j < 8; ++j) {
                    int am = MASKc[m], bm = MASKc[j];
                    int sw = __popc((am >> 1) & bm) + __popc((am >> 2) & bm);
                    float sg = (sw & 1) ? -1.f : 1.f;
                    q += sg * gwr[MASKc[am ^ bm]] * mvv[j];
                }
                Q[m] = q;
            }
            float pvv[8];
#pragma unroll
            for (int j = 0; j < 8; ++j) {
                float pv = 0.f;
#pragma unroll
                for (int i = 0; i < 8; ++i) {
                    int am = MASKc[i], bm = MASKc[j];
                    int sw = __popc((am >> 1) & bm) + __popc((am >> 2) & bm);
                    float sg = (sw & 1) ? -1.f : 1.f;
                    pv += sg * mpv[i] * Q[MASKc[am ^ bm]];
                }
                pvv[j] = pv;
            }
#pragma unroll
            for (int j = 0; j < 8; j += 2) {
                uint32_t hh, ll;
                split2h(pvv[j], pvv[j + 1], hh, ll);
                char* base = smem + OFF_X + row * 272 + (k >> 1) * 64 + (k & 1) * 16 + j * 2;
                *(uint32_t*)(base)      = hh;
                *(uint32_t*)(base + 32) = ll;
            }
        }
    }
    __syncthreads();

    // ===== T-GEMM: out[64,95] = P[64,64] @ Tt[64,96], prefetch-pipelined =====
    {
        float a3[6][4];
#pragma unroll
        for (int j = 0; j < 6; ++j)
#pragma unroll
            for (int q = 0; q < 4; ++q) a3[j][q] = 0.f;

        const int arow2 = wm2 * 16 + arow1;
        uint32_t PH[2][4], PL[2][4];
        uint2 TF[2][6];
        {
            uint32_t ao = sb + OFF_X + (uint32_t)(arow2 * 272) + acolb;
            ldsm4(PH[0], ao);
            ldsm4(PL[0], ao + 32);
#pragma unroll
            for (int j2 = 0; j2 < 6; ++j2)
                TF[0][j2] = *(const uint2*)(g_ttf + (wn2 * 48 + j2 * 8 + g) * 32 + 2 * t);
        }
#pragma unroll
        for (int s = 0; s < 4; ++s) {
            int cur = s & 1, nxt = cur ^ 1;
            if (s < 3) {
                int sn = s + 1;
                uint32_t ao = sb + OFF_X + (uint32_t)(arow2 * 272 + sn * 64) + acolb;
                ldsm4(PH[nxt], ao);
                ldsm4(PL[nxt], ao + 32);
#pragma unroll
                for (int j2 = 0; j2 < 6; ++j2)
                    TF[nxt][j2] = *(const uint2*)(g_ttf + (wn2 * 48 + j2 * 8 + g) * 32
                                  + sn * 8 + 2 * t);
            }
#pragma unroll
            for (int j2 = 0; j2 < 6; ++j2)
                mma16816(a3[j2], PH[cur], TF[cur][j2].x, TF[cur][j2].y);
#pragma unroll
            for (int j2 = 0; j2 < 6; ++j2)
                mma16816(a3[j2], PL[cur], TF[cur][j2].x, TF[cur][j2].y);
        }
        int rowt = r0 + wm2 * 16 + g;
#pragma unroll
        for (int j2 = 0; j2 < 6; ++j2) {
            int col = wn2 * 48 + j2 * 8 + 2 * t;
            if (col < 95) {
                out[(size_t)rowt * 95 + col]       = a3[j2][0];
                out[(size_t)(rowt + 8) * 95 + col] = a3[j2][2];
            }
            if (col + 1 < 95) {
                out[(size_t)rowt * 95 + col + 1]       = a3[j2][1];
                out[(size_t)(rowt + 8) * 95 + col + 1] = a3[j2][3];
            }
        }
    }
}

extern "C" void kernel_launch(void* const* d_in, const int* in_sizes, int n_in,
                              void* d_out, int out_size) {
    const float* h_perp = (const float*)d_in[0];
    const float* h_vuln = (const float*)d_in[1];
    const float* Wp1 = (const float*)d_in[2];
    const float* bp1 = (const float*)d_in[3];
    const float* lgp = (const float*)d_in[4];
    const float* lbp = (const float*)d_in[5];
    const float* Wp2 = (const float*)d_in[6];
    const float* bp2 = (const float*)d_in[7];
    const float* Wv1 = (const float*)d_in[8];
    const float* bv1 = (const float*)d_in[9];
    const float* lgv = (const float*)d_in[10];
    const float* lbv = (const float*)d_in[11];
    const float* Wv2 = (const float*)d_in[12];
    const float* bv2 = (const float*)d_in[13];
    const float* Tm  = (const float*)d_in[14];
    const float* gw  = (const float*)d_in[15];
    float* out = (float*)d_out;

    int B = in_sizes[0] / 512;   // 16384
    int grid = B / TB;           // 256 (single wave at 2 CTAs/SM)

    prep_kernel<<<(65536 + 8192 + 3072 + 255) / 256, 256>>>(Wp1, Wv1, Wp2, Wv2, Tm);

    cudaFuncSetAttribute(clifford_mma_kernel,
                         cudaFuncAttributeMaxDynamicSharedMemorySize, SMEM_BYTES);
    clifford_mma_kernel<<<grid, NT, SMEM_BYTES>>>(
        h_perp, h_vuln, bp1, lgp, lbp, bp2, bv1, lgv, lbv, bv2, gw, out);
}